// round 1
// baseline (speedup 1.0000x reference)
#include <cuda_runtime.h>

#define BB   4
#define NPTS 2048
#define MPTS 2048

// ---------------- device scratch (no allocations) ----------------
__device__ float4 g_P0[BB * NPTS];  // x_t0,      w = |p|^2
__device__ float4 g_P1[BB * NPTS];  // x_t1
__device__ float4 g_PH[BB * NPTS];  // x_t1_hat = x_t0 + m_hat
__device__ float4 g_Y [BB * MPTS];  // y0 = y_hat0[:,0]
__device__ float  g_chamfer[BB];    // sum of dist1 + dist2 row-mins per batch
__device__ float  g_min1[BB * MPTS];
__device__ float  g_min2[BB * MPTS];
__device__ int    g_idx [BB * MPTS];
__device__ float  g_dyn;
__device__ float  g_stat;
__device__ float  g_sumd;
__device__ int    g_cntd;

// ---------------- helpers ----------------
__device__ __forceinline__ float warp_min(float v) {
#pragma unroll
    for (int o = 16; o; o >>= 1)
        v = fminf(v, __shfl_xor_sync(0xffffffffu, v, o));
    return v;
}

__device__ __forceinline__ void warp_min_arg(float& v, int& i) {
#pragma unroll
    for (int o = 16; o; o >>= 1) {
        float ov = __shfl_xor_sync(0xffffffffu, v, o);
        int   oi = __shfl_xor_sync(0xffffffffu, i, o);
        if (ov < v || (ov == v && oi < i)) { v = ov; i = oi; }
    }
}

// min over columns of squared dist, 4 rows per warp
__device__ __forceinline__ void rowmin4(const float4* p, const float4* __restrict__ cols,
                                        int ncols, int lane, float* best) {
#pragma unroll 4
    for (int c = lane; c < ncols; c += 32) {
        float4 q = __ldg(&cols[c]);
#pragma unroll
        for (int j = 0; j < 4; j++) {
            float dot = p[j].x * q.x + p[j].y * q.y + p[j].z * q.z;
            float d   = fmaxf(fmaf(-2.f, dot, p[j].w + q.w), 0.f);
            best[j]   = fminf(best[j], d);
        }
    }
}

__device__ __forceinline__ void rowmin4_arg(const float4* p, const float4* __restrict__ cols,
                                            int ncols, int lane, float* best, int* bidx) {
#pragma unroll 2
    for (int c = lane; c < ncols; c += 32) {
        float4 q = __ldg(&cols[c]);
#pragma unroll
        for (int j = 0; j < 4; j++) {
            float dot = p[j].x * q.x + p[j].y * q.y + p[j].z * q.z;
            float d   = fmaxf(fmaf(-2.f, dot, p[j].w + q.w), 0.f);
            if (d < best[j]) { best[j] = d; bidx[j] = c; }
        }
    }
}

// ---------------- kernels ----------------
__global__ void k_zero() {
    int t = threadIdx.x;
    if (t < BB) g_chamfer[t] = 0.f;
    if (t == 0) { g_dyn = 0.f; g_stat = 0.f; g_sumd = 0.f; g_cntd = 0; }
}

__global__ void k_prep(const float* __restrict__ x, const float* __restrict__ mh,
                       const float* __restrict__ y0) {
    int i = blockIdx.x * blockDim.x + threadIdx.x;
    if (i >= BB * NPTS) return;
    int b = i / NPTS, n = i % NPTS;
    const float* p0 = x  + ((size_t)(b * 2 + 0) * NPTS + n) * 3;
    const float* p1 = x  + ((size_t)(b * 2 + 1) * NPTS + n) * 3;
    const float* pm = mh + ((size_t)b * NPTS + n) * 3;
    const float* py = y0 + ((size_t)b * MPTS + n) * 3;
    float a0x = p0[0], a0y = p0[1], a0z = p0[2];
    float a1x = p1[0], a1y = p1[1], a1z = p1[2];
    float ahx = a0x + pm[0], ahy = a0y + pm[1], ahz = a0z + pm[2];
    float yx = py[0], yy = py[1], yz = py[2];
    g_P0[i] = make_float4(a0x, a0y, a0z, a0x * a0x + a0y * a0y + a0z * a0z);
    g_P1[i] = make_float4(a1x, a1y, a1z, a1x * a1x + a1y * a1y + a1z * a1z);
    g_PH[i] = make_float4(ahx, ahy, ahz, ahx * ahx + ahy * ahy + ahz * ahz);
    g_Y [i] = make_float4(yx,  yy,  yz,  yx * yx + yy * yy + yz * yz);
}

// dir 0: rows = x_t1_hat, cols = x_t1  (dist1 row-mins)
// dir 1: rows = x_t1,     cols = x_t1_hat  (dist2 == col-mins of d)
__global__ void k_chamfer() {
    int b   = blockIdx.z;
    int dir = blockIdx.y;
    const float4* rows = (dir == 0) ? (g_PH + b * NPTS) : (g_P1 + b * NPTS);
    const float4* cols = (dir == 0) ? (g_P1 + b * NPTS) : (g_PH + b * NPTS);
    int warp = threadIdx.x >> 5, lane = threadIdx.x & 31;
    int r0 = blockIdx.x * 32 + warp * 4;
    float4 p[4];
#pragma unroll
    for (int j = 0; j < 4; j++) p[j] = rows[r0 + j];
    float best[4] = {1e30f, 1e30f, 1e30f, 1e30f};
    rowmin4(p, cols, NPTS, lane, best);
    float s = 0.f;
#pragma unroll
    for (int j = 0; j < 4; j++) s += warp_min(best[j]);
    if (lane == 0) atomicAdd(&g_chamfer[b], s);
}

// per y0 row: min+argmin over x_t0, min over x_t1
__global__ void k_ymins() {
    int b = blockIdx.z;
    int warp = threadIdx.x >> 5, lane = threadIdx.x & 31;
    int r0 = blockIdx.x * 32 + warp * 4;
    float4 p[4];
#pragma unroll
    for (int j = 0; j < 4; j++) p[j] = g_Y[b * MPTS + r0 + j];
    float b1[4] = {1e30f, 1e30f, 1e30f, 1e30f};
    int   bi[4] = {0, 0, 0, 0};
    rowmin4_arg(p, g_P0 + b * NPTS, NPTS, lane, b1, bi);
    float b2[4] = {1e30f, 1e30f, 1e30f, 1e30f};
    rowmin4(p, g_P1 + b * NPTS, NPTS, lane, b2);
#pragma unroll
    for (int j = 0; j < 4; j++) {
        warp_min_arg(b1[j], bi[j]);
        b2[j] = warp_min(b2[j]);
    }
    if (lane == 0) {
#pragma unroll
        for (int j = 0; j < 4; j++) {
            int o = b * MPTS + r0 + j;
            g_min1[o] = b1[j];
            g_idx [o] = bi[j];
            g_min2[o] = fminf(b1[j], b2[j]);
        }
    }
}

// c1 = min over y0 of d(x_t0, y0); masked sum / count for loss_dist
__global__ void k_c1() {
    int b = blockIdx.z;
    int warp = threadIdx.x >> 5, lane = threadIdx.x & 31;
    int r0 = blockIdx.x * 32 + warp * 4;
    float4 p[4];
#pragma unroll
    for (int j = 0; j < 4; j++) p[j] = g_P0[b * NPTS + r0 + j];
    float best[4] = {1e30f, 1e30f, 1e30f, 1e30f};
    rowmin4(p, g_Y + b * MPTS, MPTS, lane, best);
#pragma unroll
    for (int j = 0; j < 4; j++) best[j] = warp_min(best[j]);
    if (lane == 0) {
        float s = 0.f; int c = 0;
#pragma unroll
        for (int j = 0; j < 4; j++)
            if (best[j] < 0.1f) { s += best[j]; c++; }
        if (c) { atomicAdd(&g_sumd, s); atomicAdd(&g_cntd, c); }
    }
}

__global__ void k_final(const float* __restrict__ y0h, const float* __restrict__ y1h,
                        const float* __restrict__ mh) {
    int i = blockIdx.x * blockDim.x + threadIdx.x;
    float ldyn = 0.f, lsta = 0.f;
    if (i < BB * MPTS) {
        int b = i / MPTS;
        float mc = ((g_chamfer[b] * (1.f / NPTS)) < 0.1f) ? 1.f : 0.f;
        float md = (sqrtf(g_min1[i]) < 0.05f) ? 1.f : 0.f;  // match reference sqrt compare
        float mn = (sqrtf(g_min2[i]) > 0.2f)  ? 1.f : 0.f;
        int id = g_idx[i];
        float cmd = mc * md;
#pragma unroll
        for (int k = 0; k < 3; k++) {
            float dy = y1h[(size_t)i * 3 + k] - y0h[(size_t)i * 3 + k];
            float nm = mh[((size_t)b * NPTS + id) * 3 + k];
            float e  = (dy - nm) * cmd;
            ldyn += e * e;
            float s = dy * mn;
            lsta += s * s;
        }
    }
#pragma unroll
    for (int o = 16; o; o >>= 1) {
        ldyn += __shfl_xor_sync(0xffffffffu, ldyn, o);
        lsta += __shfl_xor_sync(0xffffffffu, lsta, o);
    }
    __shared__ float sd[8], ss[8];
    int warp = threadIdx.x >> 5, lane = threadIdx.x & 31;
    if (lane == 0) { sd[warp] = ldyn; ss[warp] = lsta; }
    __syncthreads();
    if (threadIdx.x == 0) {
        float a = 0.f, c = 0.f;
#pragma unroll
        for (int w = 0; w < 8; w++) { a += sd[w]; c += ss[w]; }
        atomicAdd(&g_dyn, a);
        atomicAdd(&g_stat, c);
    }
}

__global__ void k_writeout(float* __restrict__ out) {
    const float inv = 1.f / (float)(BB * MPTS * 3);
    out[0] = g_dyn  * inv;
    out[1] = g_stat * inv;
    out[2] = g_sumd / fmaxf((float)g_cntd, 1.f);
}

// ---------------- launch ----------------
extern "C" void kernel_launch(void* const* d_in, const int* in_sizes, int n_in,
                              void* d_out, int out_size) {
    const float* x   = (const float*)d_in[0];  // (B,2,N,3)
    const float* mh  = (const float*)d_in[1];  // (B,1,N,3)
    const float* y0h = (const float*)d_in[2];  // (B,1,M,3)
    const float* y1h = (const float*)d_in[3];  // (B,1,M,3)
    float* out = (float*)d_out;

    k_zero<<<1, 32>>>();
    k_prep<<<(BB * NPTS + 255) / 256, 256>>>(x, mh, y0h);
    k_chamfer<<<dim3(NPTS / 32, 2, BB), 256>>>();
    k_ymins  <<<dim3(MPTS / 32, 1, BB), 256>>>();
    k_c1     <<<dim3(NPTS / 32, 1, BB), 256>>>();
    k_final  <<<(BB * MPTS + 255) / 256, 256>>>(y0h, y1h, mh);
    k_writeout<<<1, 1>>>(out);
}

// round 2
// speedup vs baseline: 1.0121x; 1.0121x over previous
#include <cuda_runtime.h>

#define BB    4
#define NPTS  2048
#define TPB   64      // threads per pairwise block (= rows per block)

// ---------------- device scratch (no allocations) ----------------
__device__ float4 g_P0[BB * NPTS];   // x_t0      (x,y,z,|p|^2)
__device__ float4 g_P1[BB * NPTS];   // x_t1
__device__ float4 g_PH[BB * NPTS];   // x_t1_hat = x_t0 + m_hat
__device__ float4 g_Y [BB * NPTS];   // y0
__device__ float  g_chamfer[BB];
__device__ float  g_min1 [BB * NPTS];
__device__ float  g_min2b[BB * NPTS];
__device__ int    g_idx  [BB * NPTS];
__device__ float  g_sumd;
__device__ int    g_cntd;

// ---------------- prep: pack points + zero accumulators ----------------
__global__ void k_prep(const float* __restrict__ x, const float* __restrict__ mh,
                       const float* __restrict__ y0) {
    int i = blockIdx.x * blockDim.x + threadIdx.x;
    if (i >= BB * NPTS) return;
    if (i == 0) {
        g_chamfer[0] = g_chamfer[1] = g_chamfer[2] = g_chamfer[3] = 0.f;
        g_sumd = 0.f; g_cntd = 0;
    }
    int b = i / NPTS, n = i % NPTS;
    const float* p0 = x  + ((size_t)(b * 2 + 0) * NPTS + n) * 3;
    const float* p1 = x  + ((size_t)(b * 2 + 1) * NPTS + n) * 3;
    const float* pm = mh + ((size_t)b * NPTS + n) * 3;
    const float* py = y0 + ((size_t)b * NPTS + n) * 3;
    float a0x = p0[0], a0y = p0[1], a0z = p0[2];
    float a1x = p1[0], a1y = p1[1], a1z = p1[2];
    float ahx = a0x + pm[0], ahy = a0y + pm[1], ahz = a0z + pm[2];
    float yx = py[0], yy = py[1], yz = py[2];
    g_P0[i] = make_float4(a0x, a0y, a0z, a0x*a0x + a0y*a0y + a0z*a0z);
    g_P1[i] = make_float4(a1x, a1y, a1z, a1x*a1x + a1y*a1y + a1z*a1z);
    g_PH[i] = make_float4(ahx, ahy, ahz, ahx*ahx + ahy*ahy + ahz*ahz);
    g_Y [i] = make_float4(yx,  yy,  yz,  yx*yx  + yy*yy  + yz*yz);
}

// ---------------- fused pairwise kernel ----------------
// task 0: rows PH, cols P1  -> chamfer dist1 sum
// task 1: rows P1, cols PH  -> chamfer dist2 sum
// task 2: rows Y , cols P0  -> min1 + argmin
// task 3: rows Y , cols P1  -> min2b
// task 4: rows P0, cols Y   -> c1 masked sum/count
__global__ void __launch_bounds__(TPB) k_pair() {
    __shared__ float4 sc[NPTS];                      // 32 KB: scaled columns
    int task = blockIdx.z, b = blockIdx.y;
    const float4* rows;
    const float4* cols;
    switch (task) {
        case 0:  rows = g_PH + b*NPTS; cols = g_P1 + b*NPTS; break;
        case 1:  rows = g_P1 + b*NPTS; cols = g_PH + b*NPTS; break;
        case 2:  rows = g_Y  + b*NPTS; cols = g_P0 + b*NPTS; break;
        case 3:  rows = g_Y  + b*NPTS; cols = g_P1 + b*NPTS; break;
        default: rows = g_P0 + b*NPTS; cols = g_Y  + b*NPTS; break;
    }
    // stage columns, pre-scaled so inner loop is pure FFMA:
    // d' = qw + (-2qx)px + (-2qy)py + (-2qz)pz ; true d = max(d' + pw, 0)
    for (int i = threadIdx.x; i < NPTS; i += TPB) {
        float4 q = cols[i];
        sc[i] = make_float4(-2.f * q.x, -2.f * q.y, -2.f * q.z, q.w);
    }
    __syncthreads();

    int r = blockIdx.x * TPB + threadIdx.x;
    float4 p = rows[r];
    float best = 1e30f;
    int   idx  = 0;

    if (task == 2) {
        // strict < with ascending scan == first-occurrence argmin
#pragma unroll 4
        for (int c = 0; c < NPTS; c++) {
            float4 q = sc[c];
            float d = fmaf(q.x, p.x, fmaf(q.y, p.y, fmaf(q.z, p.z, q.w)));
            bool lt = d < best;
            idx  = lt ? c : idx;
            best = lt ? d : best;
        }
    } else {
#pragma unroll 8
        for (int c = 0; c < NPTS; c++) {
            float4 q = sc[c];
            float d = fmaf(q.x, p.x, fmaf(q.y, p.y, fmaf(q.z, p.z, q.w)));
            best = fminf(best, d);
        }
    }
    float dmin = fmaxf(best + p.w, 0.f);   // restore +|p|^2 and clamp (monotone)

    int lane = threadIdx.x & 31;
    if (task == 0 || task == 1) {
        float s = dmin;
#pragma unroll
        for (int o = 16; o; o >>= 1) s += __shfl_xor_sync(0xffffffffu, s, o);
        if (lane == 0) atomicAdd(&g_chamfer[b], s);
    } else if (task == 2) {
        g_min1[b * NPTS + r] = dmin;
        g_idx [b * NPTS + r] = idx;
    } else if (task == 3) {
        g_min2b[b * NPTS + r] = dmin;
    } else {
        float v = (dmin < 0.1f) ? dmin : 0.f;
        float c = (dmin < 0.1f) ? 1.f  : 0.f;
#pragma unroll
        for (int o = 16; o; o >>= 1) {
            v += __shfl_xor_sync(0xffffffffu, v, o);
            c += __shfl_xor_sync(0xffffffffu, c, o);
        }
        if (lane == 0) {
            atomicAdd(&g_sumd, v);
            atomicAdd(&g_cntd, (int)c);
        }
    }
}

// ---------------- final: masks + losses + writeout (single block) ----------------
__global__ void k_final(const float* __restrict__ y0h, const float* __restrict__ y1h,
                        const float* __restrict__ mh, float* __restrict__ out) {
    float ldyn = 0.f, lsta = 0.f;
    for (int i = threadIdx.x; i < BB * NPTS; i += 1024) {
        int b = i >> 11;
        float mc = ((g_chamfer[b] * (1.f / NPTS)) < 0.1f) ? 1.f : 0.f;
        float m1 = g_min1[i];
        float md = (sqrtf(m1) < 0.05f) ? 1.f : 0.f;
        float mn = (sqrtf(fminf(m1, g_min2b[i])) > 0.2f) ? 1.f : 0.f;
        int   id = g_idx[i];
        float cmd = mc * md;
#pragma unroll
        for (int k = 0; k < 3; k++) {
            float dy = y1h[(size_t)i * 3 + k] - y0h[(size_t)i * 3 + k];
            float nm = mh[((size_t)b * NPTS + id) * 3 + k];
            float e  = (dy - nm) * cmd;
            ldyn = fmaf(e, e, ldyn);
            float s = dy * mn;
            lsta = fmaf(s, s, lsta);
        }
    }
#pragma unroll
    for (int o = 16; o; o >>= 1) {
        ldyn += __shfl_xor_sync(0xffffffffu, ldyn, o);
        lsta += __shfl_xor_sync(0xffffffffu, lsta, o);
    }
    __shared__ float sd[32], ss[32];
    int warp = threadIdx.x >> 5, lane = threadIdx.x & 31;
    if (lane == 0) { sd[warp] = ldyn; ss[warp] = lsta; }
    __syncthreads();
    if (threadIdx.x == 0) {
        float a = 0.f, c = 0.f;
#pragma unroll
        for (int w = 0; w < 32; w++) { a += sd[w]; c += ss[w]; }
        const float inv = 1.f / (float)(BB * NPTS * 3);
        out[0] = a * inv;
        out[1] = c * inv;
        out[2] = g_sumd / fmaxf((float)g_cntd, 1.f);
    }
}

// ---------------- launch ----------------
extern "C" void kernel_launch(void* const* d_in, const int* in_sizes, int n_in,
                              void* d_out, int out_size) {
    const float* x   = (const float*)d_in[0];
    const float* mh  = (const float*)d_in[1];
    const float* y0h = (const float*)d_in[2];
    const float* y1h = (const float*)d_in[3];
    float* out = (float*)d_out;

    k_prep<<<(BB * NPTS + 127) / 128, 128>>>(x, mh, y0h);
    k_pair<<<dim3(NPTS / TPB, BB, 5), TPB>>>();
    k_final<<<1, 1024>>>(y0h, y1h, mh, out);
}

// round 3
// speedup vs baseline: 1.4140x; 1.3971x over previous
#include <cuda_runtime.h>

#define BB    4
#define NPTS  2048
#define TPB   256
#define RC    4                    // row chunks
#define CC    4                    // col chunks
#define COLS_PER_BLK (NPTS / CC)   // 512
#define NPAIR (COLS_PER_BLK / 2)   // 256
#define ROWS_PER_BLK (NPTS / RC)   // 512

typedef unsigned long long u64;
typedef unsigned int       u32;

// ---- atomic-combine arrays: identity is 0 (inverted-bits max == min). ----
// Zero at module load; k_final re-zeros after reading -> deterministic replays.
__device__ u32 g_d1[BB * NPTS];   // task0: chamfer dist1 row-mins   (~bits)
__device__ u32 g_d2[BB * NPTS];   // task1: chamfer dist2 row-mins
__device__ u64 g_m1[BB * NPTS];   // task2: ~((dbits<<32)|idx)  min+argmin
__device__ u32 g_m2[BB * NPTS];   // task3: min d(y0, x_t1)
__device__ u32 g_c1[BB * NPTS];   // task4: c1 row-mins

// ---------------- f32x2 helpers ----------------
__device__ __forceinline__ u64 pack2(float lo, float hi) {
    u64 r; asm("mov.b64 %0, {%1,%2};" : "=l"(r) : "f"(lo), "f"(hi)); return r;
}
__device__ __forceinline__ void unpack2(u64 v, float& lo, float& hi) {
    asm("mov.b64 {%0,%1}, %2;" : "=f"(lo), "=f"(hi) : "l"(v));
}
__device__ __forceinline__ u64 fma2(u64 a, u64 b, u64 c) {
    u64 d; asm("fma.rn.f32x2 %0, %1, %2, %3;" : "=l"(d) : "l"(a), "l"(b), "l"(c)); return d;
}

// ---------------- fused pairwise kernel ----------------
// task 0: rows PH, cols P1   task 1: rows P1, cols PH
// task 2: rows Y,  cols P0 (argmin)   task 3: rows Y, cols P1
// task 4: rows P0, cols Y
__global__ void __launch_bounds__(TPB) k_pair(const float* __restrict__ x,
                                              const float* __restrict__ mh,
                                              const float* __restrict__ y0) {
    __shared__ ulonglong2 sA[NPAIR];   // (x0,x1),(y0,y1)  pre-scaled by -2
    __shared__ ulonglong2 sB[NPAIR];   // (z0,z1),(w0,w1)  w = |q|^2
    const int task = blockIdx.z, b = blockIdx.y;
    const int rc = blockIdx.x >> 2, cc = blockIdx.x & 3;
    const int t = threadIdx.x;

    // ---- stage this block's 512 columns (2 per thread), scaled ----
    {
        int c0 = cc * COLS_PER_BLK + 2 * t;
        const float* src;
        bool addm = false;
        if (task == 1)      { src = x  + ((size_t)(b * 2 + 0) * NPTS + c0) * 3; addm = true; } // PH
        else if (task == 2) { src = x  + ((size_t)(b * 2 + 0) * NPTS + c0) * 3; }              // P0
        else if (task == 4) { src = y0 + ((size_t)b * NPTS + c0) * 3; }                        // Y
        else                { src = x  + ((size_t)(b * 2 + 1) * NPTS + c0) * 3; }              // P1
        const float2* s2 = (const float2*)src;
        float2 aa = s2[0], bb = s2[1], cc2 = s2[2];
        float px0 = aa.x, py0 = aa.y, pz0 = bb.x;
        float px1 = bb.y, py1 = cc2.x, pz1 = cc2.y;
        if (addm) {
            const float2* m2p = (const float2*)(mh + ((size_t)b * NPTS + c0) * 3);
            float2 ma = m2p[0], mb = m2p[1], mc = m2p[2];
            px0 += ma.x; py0 += ma.y; pz0 += mb.x;
            px1 += mb.y; py1 += mc.x; pz1 += mc.y;
        }
        float w0c = px0 * px0 + py0 * py0 + pz0 * pz0;
        float w1c = px1 * px1 + py1 * py1 + pz1 * pz1;
        sA[t] = make_ulonglong2(pack2(-2.f * px0, -2.f * px1), pack2(-2.f * py0, -2.f * py1));
        sB[t] = make_ulonglong2(pack2(-2.f * pz0, -2.f * pz1), pack2(w0c, w1c));
    }

    // ---- this thread's 2 rows ----
    const int r0 = rc * ROWS_PER_BLK + t;
    const int r1 = r0 + TPB;
    float q0x, q0y, q0z, q1x, q1y, q1z;
    {
        const float* s0; const float* s1; bool addm = false;
        if (task == 0)      { s0 = x + ((size_t)(b*2+0)*NPTS + r0)*3; s1 = x + ((size_t)(b*2+0)*NPTS + r1)*3; addm = true; } // PH
        else if (task == 1) { s0 = x + ((size_t)(b*2+1)*NPTS + r0)*3; s1 = x + ((size_t)(b*2+1)*NPTS + r1)*3; }             // P1
        else if (task == 4) { s0 = x + ((size_t)(b*2+0)*NPTS + r0)*3; s1 = x + ((size_t)(b*2+0)*NPTS + r1)*3; }             // P0
        else                { s0 = y0 + ((size_t)b*NPTS + r0)*3;      s1 = y0 + ((size_t)b*NPTS + r1)*3; }                  // Y
        q0x = s0[0]; q0y = s0[1]; q0z = s0[2];
        q1x = s1[0]; q1y = s1[1]; q1z = s1[2];
        if (addm) {
            const float* m0 = mh + ((size_t)b * NPTS + r0) * 3;
            const float* m1 = mh + ((size_t)b * NPTS + r1) * 3;
            q0x += m0[0]; q0y += m0[1]; q0z += m0[2];
            q1x += m1[0]; q1y += m1[1]; q1z += m1[2];
        }
    }
    const float w0 = q0x*q0x + q0y*q0y + q0z*q0z;
    const float w1 = q1x*q1x + q1y*q1y + q1z*q1z;
    const u64 p0x2 = pack2(q0x, q0x), p0y2 = pack2(q0y, q0y), p0z2 = pack2(q0z, q0z);
    const u64 p1x2 = pack2(q1x, q1x), p1y2 = pack2(q1y, q1y), p1z2 = pack2(q1z, q1z);

    __syncthreads();

    const int base = b * NPTS;
    if (task == 2) {
        // min + first-occurrence argmin (even/odd interleaved chains)
        float bA0 = 1e30f, bB0 = 1e30f, bA1 = 1e30f, bB1 = 1e30f;
        int   iA0 = 0, iB0 = 0, iA1 = 0, iB1 = 0;
#pragma unroll 4
        for (int j = 0; j < NPAIR; j++) {
            ulonglong2 xy = sA[j];
            ulonglong2 zw = sB[j];
            u64 a0 = fma2(xy.x, p0x2, fma2(xy.y, p0y2, fma2(zw.x, p0z2, zw.y)));
            u64 a1 = fma2(xy.x, p1x2, fma2(xy.y, p1y2, fma2(zw.x, p1z2, zw.y)));
            float l0, h0, l1, h1;
            unpack2(a0, l0, h0); unpack2(a1, l1, h1);
            if (l0 < bA0) { bA0 = l0; iA0 = j; }
            if (h0 < bB0) { bB0 = h0; iB0 = j; }
            if (l1 < bA1) { bA1 = l1; iA1 = j; }
            if (h1 < bB1) { bB1 = h1; iB1 = j; }
        }
        int cbase = cc * COLS_PER_BLK;
        // row 0 combine (tie -> smaller index)
        {
            float bst = bA0; int idx = 2 * iA0;
            float bo = bB0;  int io = 2 * iB0 + 1;
            if (bo < bst || (bo == bst && io < idx)) { bst = bo; idx = io; }
            float d = fmaxf(bst + w0, 0.f);
            u64 pk = ((u64)__float_as_uint(d) << 32) | (u32)(cbase + idx);
            atomicMax(&g_m1[base + r0], ~pk);
        }
        {
            float bst = bA1; int idx = 2 * iA1;
            float bo = bB1;  int io = 2 * iB1 + 1;
            if (bo < bst || (bo == bst && io < idx)) { bst = bo; idx = io; }
            float d = fmaxf(bst + w1, 0.f);
            u64 pk = ((u64)__float_as_uint(d) << 32) | (u32)(cbase + idx);
            atomicMax(&g_m1[base + r1], ~pk);
        }
    } else {
        float bA0 = 1e30f, bB0 = 1e30f, bA1 = 1e30f, bB1 = 1e30f;
#pragma unroll 4
        for (int j = 0; j < NPAIR; j++) {
            ulonglong2 xy = sA[j];
            ulonglong2 zw = sB[j];
            u64 a0 = fma2(xy.x, p0x2, fma2(xy.y, p0y2, fma2(zw.x, p0z2, zw.y)));
            u64 a1 = fma2(xy.x, p1x2, fma2(xy.y, p1y2, fma2(zw.x, p1z2, zw.y)));
            float l0, h0, l1, h1;
            unpack2(a0, l0, h0); unpack2(a1, l1, h1);
            bA0 = fminf(bA0, l0); bB0 = fminf(bB0, h0);
            bA1 = fminf(bA1, l1); bB1 = fminf(bB1, h1);
        }
        float d0 = fmaxf(fminf(bA0, bB0) + w0, 0.f);
        float d1 = fmaxf(fminf(bA1, bB1) + w1, 0.f);
        u32* arr = (task == 0) ? g_d1 : (task == 1) ? g_d2 : (task == 3) ? g_m2 : g_c1;
        atomicMax(&arr[base + r0], ~__float_as_uint(d0));
        atomicMax(&arr[base + r1], ~__float_as_uint(d1));
    }
}

// ---------------- final: reductions, masks, losses, writeout, reset ----------------
__global__ void k_final(const float* __restrict__ y0h, const float* __restrict__ y1h,
                        const float* __restrict__ mh, float* __restrict__ out) {
    __shared__ float s_ch[BB], s_mc[BB];
    __shared__ float s_sd, s_cd, s_dyn, s_stat;
    int tid = threadIdx.x, lane = tid & 31;
    if (tid < BB) s_ch[tid] = 0.f;
    if (tid == 0) { s_sd = 0.f; s_cd = 0.f; s_dyn = 0.f; s_stat = 0.f; }
    __syncthreads();

    // phase 1: chamfer sums + loss_dist masked sum/count (+ reset)
    float ch0 = 0.f, ch1 = 0.f, ch2 = 0.f, ch3 = 0.f, sd = 0.f, cd = 0.f;
    for (int i = tid; i < BB * NPTS; i += 1024) {
        int b = i >> 11;
        float d1 = __uint_as_float(~g_d1[i]);
        float d2 = __uint_as_float(~g_d2[i]);
        float s = d1 + d2;
        if (b == 0) ch0 += s; else if (b == 1) ch1 += s; else if (b == 2) ch2 += s; else ch3 += s;
        float c1 = __uint_as_float(~g_c1[i]);
        if (c1 < 0.1f) { sd += c1; cd += 1.f; }
        g_d1[i] = 0u; g_d2[i] = 0u; g_c1[i] = 0u;
    }
#pragma unroll
    for (int o = 16; o; o >>= 1) {
        ch0 += __shfl_xor_sync(0xffffffffu, ch0, o);
        ch1 += __shfl_xor_sync(0xffffffffu, ch1, o);
        ch2 += __shfl_xor_sync(0xffffffffu, ch2, o);
        ch3 += __shfl_xor_sync(0xffffffffu, ch3, o);
        sd  += __shfl_xor_sync(0xffffffffu, sd,  o);
        cd  += __shfl_xor_sync(0xffffffffu, cd,  o);
    }
    if (lane == 0) {
        atomicAdd(&s_ch[0], ch0); atomicAdd(&s_ch[1], ch1);
        atomicAdd(&s_ch[2], ch2); atomicAdd(&s_ch[3], ch3);
        atomicAdd(&s_sd, sd);     atomicAdd(&s_cd, cd);
    }
    __syncthreads();
    if (tid < BB) s_mc[tid] = ((s_ch[tid] * (1.f / NPTS)) < 0.1f) ? 1.f : 0.f;
    __syncthreads();

    // phase 2: dynamic/static losses (+ reset)
    float ldyn = 0.f, lsta = 0.f;
    for (int i = tid; i < BB * NPTS; i += 1024) {
        int b = i >> 11;
        u64 pk = ~g_m1[i];
        float m1 = __uint_as_float((u32)(pk >> 32));
        int   id = (int)(u32)pk;
        float m2 = __uint_as_float(~g_m2[i]);
        float md = (sqrtf(m1) < 0.05f) ? 1.f : 0.f;
        float mn = (sqrtf(fminf(m1, m2)) > 0.2f) ? 1.f : 0.f;
        float cmd = s_mc[b] * md;
#pragma unroll
        for (int k = 0; k < 3; k++) {
            float dy = y1h[(size_t)i * 3 + k] - y0h[(size_t)i * 3 + k];
            float nm = mh[((size_t)b * NPTS + id) * 3 + k];
            float e  = (dy - nm) * cmd;
            ldyn = fmaf(e, e, ldyn);
            float ss = dy * mn;
            lsta = fmaf(ss, ss, lsta);
        }
        g_m1[i] = 0ull; g_m2[i] = 0u;
    }
#pragma unroll
    for (int o = 16; o; o >>= 1) {
        ldyn += __shfl_xor_sync(0xffffffffu, ldyn, o);
        lsta += __shfl_xor_sync(0xffffffffu, lsta, o);
    }
    if (lane == 0) { atomicAdd(&s_dyn, ldyn); atomicAdd(&s_stat, lsta); }
    __syncthreads();
    if (tid == 0) {
        const float inv = 1.f / (float)(BB * NPTS * 3);
        out[0] = s_dyn  * inv;
        out[1] = s_stat * inv;
        out[2] = s_sd / fmaxf(s_cd, 1.f);
    }
}

// ---------------- launch: 2 kernels total ----------------
extern "C" void kernel_launch(void* const* d_in, const int* in_sizes, int n_in,
                              void* d_out, int out_size) {
    const float* x   = (const float*)d_in[0];  // (B,2,N,3)
    const float* mh  = (const float*)d_in[1];  // (B,1,N,3)
    const float* y0h = (const float*)d_in[2];  // (B,1,M,3)
    const float* y1h = (const float*)d_in[3];  // (B,1,M,3)
    float* out = (float*)d_out;

    k_pair<<<dim3(RC * CC, BB, 5), TPB>>>(x, mh, y0h);
    k_final<<<1, 1024>>>(y0h, y1h, mh, out);
}

// round 5
// speedup vs baseline: 1.5884x; 1.1233x over previous
#include <cuda_runtime.h>

#define BB    4
#define NPTS  2048
#define TPB   128
#define RC    8                     // row chunks per (task,batch)
#define ROWS_PER_BLK (NPTS / RC)    // 256 = TPB * 2 rows per block
#define NPAIR (NPTS / 2)            // 1024 column pairs staged per block

typedef unsigned long long u64;
typedef unsigned int       u32;

// ---------------- device scratch (no allocations) ----------------
__device__ float g_min1[BB * NPTS];   // plain stores, overwritten each replay
__device__ int   g_idx [BB * NPTS];
__device__ float g_min2[BB * NPTS];
__device__ float g_chamfer[BB];       // accumulators: zero at load, reset by k_write
__device__ float g_sumd;
__device__ int   g_cntd;
__device__ float g_dyn, g_stat;

// ---------------- f32x2 helpers ----------------
__device__ __forceinline__ u64 pack2(float lo, float hi) {
    u64 r; asm("mov.b64 %0, {%1,%2};" : "=l"(r) : "f"(lo), "f"(hi)); return r;
}
__device__ __forceinline__ void unpack2(u64 v, float& lo, float& hi) {
    asm("mov.b64 {%0,%1}, %2;" : "=f"(lo), "=f"(hi) : "l"(v));
}
__device__ __forceinline__ u64 fma2(u64 a, u64 b, u64 c) {
    u64 d; asm("fma.rn.f32x2 %0, %1, %2, %3;" : "=l"(d) : "l"(a), "l"(b), "l"(c)); return d;
}

// ---------------- fused pairwise kernel (columns complete per block) ----------
// task 0: rows PH, cols P1  -> chamfer dist1   task 1: rows P1, cols PH -> dist2
// task 2: rows Y,  cols P0  -> min1 + argmin   task 3: rows Y,  cols P1 -> min2
// task 4: rows P0, cols Y   -> loss_dist sum/count
__global__ void __launch_bounds__(TPB) k_pair(const float* __restrict__ x,
                                              const float* __restrict__ mh,
                                              const float* __restrict__ y0) {
    __shared__ ulonglong2 sA[NPAIR];   // (x0,x1),(y0,y1)  scaled by -2
    __shared__ ulonglong2 sB[NPAIR];   // (z0,z1),(w0,w1)  w = |q|^2
    const int task = blockIdx.z, b = blockIdx.y, rc = blockIdx.x;
    const int t = threadIdx.x;

    // ---- stage ALL 2048 columns, pre-scaled (8 pairs per thread) ----
    {
        const float* src; bool addm = false;
        if (task == 1)      { src = x  + (size_t)(b*2+0)*NPTS*3; addm = true; }   // PH
        else if (task == 2) { src = x  + (size_t)(b*2+0)*NPTS*3; }                // P0
        else if (task == 4) { src = y0 + (size_t)b*NPTS*3; }                      // Y
        else                { src = x  + (size_t)(b*2+1)*NPTS*3; }                // P1
        for (int i = t; i < NPAIR; i += TPB) {
            const float2* s2 = (const float2*)(src + (size_t)2 * i * 3);
            float2 aa = s2[0], bb = s2[1], cc = s2[2];
            float px0 = aa.x, py0 = aa.y, pz0 = bb.x;
            float px1 = bb.y, py1 = cc.x, pz1 = cc.y;
            if (addm) {
                const float2* m2p = (const float2*)(mh + ((size_t)b*NPTS + 2*i) * 3);
                float2 ma = m2p[0], mb = m2p[1], mc = m2p[2];
                px0 += ma.x; py0 += ma.y; pz0 += mb.x;
                px1 += mb.y; py1 += mc.x; pz1 += mc.y;
            }
            float w0c = px0*px0 + py0*py0 + pz0*pz0;
            float w1c = px1*px1 + py1*py1 + pz1*pz1;
            sA[i] = make_ulonglong2(pack2(-2.f*px0, -2.f*px1), pack2(-2.f*py0, -2.f*py1));
            sB[i] = make_ulonglong2(pack2(-2.f*pz0, -2.f*pz1), pack2(w0c, w1c));
        }
    }

    // ---- this thread's 2 rows ----
    const int r0 = rc * ROWS_PER_BLK + t;
    const int r1 = r0 + TPB;
    float q0x, q0y, q0z, q1x, q1y, q1z;
    {
        const float* rsrc; bool addm = false;
        if (task == 0)      { rsrc = x  + (size_t)(b*2+0)*NPTS*3; addm = true; }  // PH
        else if (task == 1) { rsrc = x  + (size_t)(b*2+1)*NPTS*3; }               // P1
        else if (task == 4) { rsrc = x  + (size_t)(b*2+0)*NPTS*3; }               // P0
        else                { rsrc = y0 + (size_t)b*NPTS*3; }                     // Y
        const float* s0 = rsrc + (size_t)r0 * 3;
        const float* s1 = rsrc + (size_t)r1 * 3;
        q0x = s0[0]; q0y = s0[1]; q0z = s0[2];
        q1x = s1[0]; q1y = s1[1]; q1z = s1[2];
        if (addm) {
            const float* m0 = mh + ((size_t)b*NPTS + r0) * 3;
            const float* m1 = mh + ((size_t)b*NPTS + r1) * 3;
            q0x += m0[0]; q0y += m0[1]; q0z += m0[2];
            q1x += m1[0]; q1y += m1[1]; q1z += m1[2];
        }
    }
    const float w0 = q0x*q0x + q0y*q0y + q0z*q0z;
    const float w1 = q1x*q1x + q1y*q1y + q1z*q1z;
    const u64 p0x2 = pack2(q0x, q0x), p0y2 = pack2(q0y, q0y), p0z2 = pack2(q0z, q0z);
    const u64 p1x2 = pack2(q1x, q1x), p1y2 = pack2(q1y, q1y), p1z2 = pack2(q1z, q1z);

    __syncthreads();

    const int base = b * NPTS;
    const int lane = t & 31;

    if (task == 2) {
        // min + first-occurrence argmin over ALL columns (finalized in-block)
        float bA0 = 1e30f, bB0 = 1e30f, bA1 = 1e30f, bB1 = 1e30f;
        int   iA0 = 0, iB0 = 0, iA1 = 0, iB1 = 0;
#pragma unroll 4
        for (int j = 0; j < NPAIR; j++) {
            ulonglong2 xy = sA[j];
            ulonglong2 zw = sB[j];
            u64 a0 = fma2(xy.x, p0x2, fma2(xy.y, p0y2, fma2(zw.x, p0z2, zw.y)));
            u64 a1 = fma2(xy.x, p1x2, fma2(xy.y, p1y2, fma2(zw.x, p1z2, zw.y)));
            float l0, h0, l1, h1;
            unpack2(a0, l0, h0); unpack2(a1, l1, h1);
            bool c0 = l0 < bA0; iA0 = c0 ? j : iA0; bA0 = c0 ? l0 : bA0;
            bool c1 = h0 < bB0; iB0 = c1 ? j : iB0; bB0 = c1 ? h0 : bB0;
            bool c2 = l1 < bA1; iA1 = c2 ? j : iA1; bA1 = c2 ? l1 : bA1;
            bool c3 = h1 < bB1; iB1 = c3 ? j : iB1; bB1 = c3 ? h1 : bB1;
        }
        {
            float bst = bA0; int idx = 2*iA0;
            float bo  = bB0; int io  = 2*iB0 + 1;
            if (bo < bst || (bo == bst && io < idx)) { bst = bo; idx = io; }
            g_min1[base + r0] = fmaxf(bst + w0, 0.f);
            g_idx [base + r0] = idx;
        }
        {
            float bst = bA1; int idx = 2*iA1;
            float bo  = bB1; int io  = 2*iB1 + 1;
            if (bo < bst || (bo == bst && io < idx)) { bst = bo; idx = io; }
            g_min1[base + r1] = fmaxf(bst + w1, 0.f);
            g_idx [base + r1] = idx;
        }
    } else {
        float bA0 = 1e30f, bB0 = 1e30f, bA1 = 1e30f, bB1 = 1e30f;
#pragma unroll 8
        for (int j = 0; j < NPAIR; j++) {
            ulonglong2 xy = sA[j];
            ulonglong2 zw = sB[j];
            u64 a0 = fma2(xy.x, p0x2, fma2(xy.y, p0y2, fma2(zw.x, p0z2, zw.y)));
            u64 a1 = fma2(xy.x, p1x2, fma2(xy.y, p1y2, fma2(zw.x, p1z2, zw.y)));
            float l0, h0, l1, h1;
            unpack2(a0, l0, h0); unpack2(a1, l1, h1);
            bA0 = fminf(bA0, l0); bB0 = fminf(bB0, h0);
            bA1 = fminf(bA1, l1); bB1 = fminf(bB1, h1);
        }
        float d0 = fmaxf(fminf(bA0, bB0) + w0, 0.f);
        float d1 = fmaxf(fminf(bA1, bB1) + w1, 0.f);

        if (task == 3) {
            g_min2[base + r0] = d0;
            g_min2[base + r1] = d1;
        } else if (task == 4) {
            float v = ((d0 < 0.1f) ? d0 : 0.f) + ((d1 < 0.1f) ? d1 : 0.f);
            int   c = (d0 < 0.1f) + (d1 < 0.1f);
#pragma unroll
            for (int o = 16; o; o >>= 1) {
                v += __shfl_xor_sync(0xffffffffu, v, o);
                c += __shfl_xor_sync(0xffffffffu, c, o);
            }
            if (lane == 0) { atomicAdd(&g_sumd, v); atomicAdd(&g_cntd, c); }
        } else { // tasks 0, 1: chamfer partial sums
            float s = d0 + d1;
#pragma unroll
            for (int o = 16; o; o >>= 1) s += __shfl_xor_sync(0xffffffffu, s, o);
            if (lane == 0) atomicAdd(&g_chamfer[b], s);
        }
    }
}

// ---------------- losses (multi-block, latency spread across chip) ----------
__global__ void k_final(const float* __restrict__ y0h, const float* __restrict__ y1h,
                        const float* __restrict__ mh) {
    int i = blockIdx.x * blockDim.x + threadIdx.x;   // 0..8191, one row each
    int b = i >> 11;
    float mc = ((g_chamfer[b] * (1.f / NPTS)) < 0.1f) ? 1.f : 0.f;
    float m1 = g_min1[i];
    int   id = g_idx[i];
    float m2 = g_min2[i];
    float md = (sqrtf(m1) < 0.05f) ? 1.f : 0.f;
    float mn = (sqrtf(fminf(m1, m2)) > 0.2f) ? 1.f : 0.f;
    float cmd = mc * md;
    float ldyn = 0.f, lsta = 0.f;
#pragma unroll
    for (int k = 0; k < 3; k++) {
        float dy = y1h[(size_t)i*3 + k] - y0h[(size_t)i*3 + k];
        float nm = mh[((size_t)b*NPTS + id)*3 + k];
        float e  = (dy - nm) * cmd;
        ldyn = fmaf(e, e, ldyn);
        float ss = dy * mn;
        lsta = fmaf(ss, ss, lsta);
    }
#pragma unroll
    for (int o = 16; o; o >>= 1) {
        ldyn += __shfl_xor_sync(0xffffffffu, ldyn, o);
        lsta += __shfl_xor_sync(0xffffffffu, lsta, o);
    }
    __shared__ float sd[8], ss2[8];
    int warp = threadIdx.x >> 5, lane = threadIdx.x & 31;
    if (lane == 0) { sd[warp] = ldyn; ss2[warp] = lsta; }
    __syncthreads();
    if (threadIdx.x == 0) {
        float a = 0.f, c = 0.f;
#pragma unroll
        for (int w = 0; w < 8; w++) { a += sd[w]; c += ss2[w]; }
        atomicAdd(&g_dyn, a);
        atomicAdd(&g_stat, c);
    }
}

// ---------------- writeout + accumulator reset (replay-safe) ---------------
__global__ void k_write(float* __restrict__ out) {
    const float inv = 1.f / (float)(BB * NPTS * 3);
    out[0] = g_dyn  * inv;
    out[1] = g_stat * inv;
    out[2] = g_sumd / fmaxf((float)g_cntd, 1.f);
    g_chamfer[0] = g_chamfer[1] = g_chamfer[2] = g_chamfer[3] = 0.f;
    g_sumd = 0.f; g_cntd = 0; g_dyn = 0.f; g_stat = 0.f;
}

// ---------------- launch: 3 kernels ----------------
extern "C" void kernel_launch(void* const* d_in, const int* in_sizes, int n_in,
                              void* d_out, int out_size) {
    const float* x   = (const float*)d_in[0];  // (B,2,N,3)
    const float* mh  = (const float*)d_in[1];  // (B,1,N,3)
    const float* y0h = (const float*)d_in[2];  // (B,1,M,3)
    const float* y1h = (const float*)d_in[3];  // (B,1,M,3)
    float* out = (float*)d_out;

    k_pair <<<dim3(RC, BB, 5), TPB>>>(x, mh, y0h);
    k_final<<<BB * NPTS / 256, 256>>>(y0h, y1h, mh);
    k_write<<<1, 1>>>(out);
}

// round 6
// speedup vs baseline: 1.7010x; 1.0709x over previous
#include <cuda_runtime.h>

#define BB    4
#define NPTS  2048
#define BBN   (BB * NPTS)
#define TPB   256
#define RC    4                      // row chunks
#define CC    2                      // column halves
#define ROWS_PER_BLK (NPTS / RC)     // 512 = 2 * TPB
#define COLS_PER_BLK (NPTS / CC)     // 1024
#define NPAIR_BLK (COLS_PER_BLK / 2) // 512 pairs staged

typedef unsigned long long u64;
typedef unsigned int       u32;

// ---------------- device scratch (plain stores, single writer per slot) ----
__device__ float g_hd[5 * CC * BBN];     // [task][half][row] half row-mins
__device__ int   g_hidx[CC * BBN];       // task2 half argmins (global col idx)
__device__ float g_min1[BBN];
__device__ int   g_idx [BBN];
__device__ float g_min2[BBN];
// accumulators: zero at load, reset by k_write every replay
__device__ float g_chamfer[BB];
__device__ float g_sumd;
__device__ int   g_cntd;
__device__ float g_dyn, g_stat;

#define HD(task, half, i) g_hd[((task) * CC + (half)) * BBN + (i)]

// ---------------- f32x2 helpers ----------------
__device__ __forceinline__ u64 pack2(float lo, float hi) {
    u64 r; asm("mov.b64 %0, {%1,%2};" : "=l"(r) : "f"(lo), "f"(hi)); return r;
}
__device__ __forceinline__ void unpack2(u64 v, float& lo, float& hi) {
    asm("mov.b64 {%0,%1}, %2;" : "=f"(lo), "=f"(hi) : "l"(v));
}
__device__ __forceinline__ u64 fma2(u64 a, u64 b, u64 c) {
    u64 d; asm("fma.rn.f32x2 %0, %1, %2, %3;" : "=l"(d) : "l"(a), "l"(b), "l"(c)); return d;
}

// ---------------- pairwise kernel: (task, batch, rowchunk, colhalf) ----------
// task 0: rows PH, cols P1   task 1: rows P1, cols PH
// task 2: rows Y,  cols P0 (argmin)   task 3: rows Y, cols P1
// task 4: rows P0, cols Y
__global__ void __launch_bounds__(TPB) k_pair(const float* __restrict__ x,
                                              const float* __restrict__ mh,
                                              const float* __restrict__ y0) {
    __shared__ ulonglong2 sA[NPAIR_BLK];   // (x0,x1),(y0,y1) scaled by -2
    __shared__ ulonglong2 sB[NPAIR_BLK];   // (z0,z1),(w0,w1) w=|q|^2
    const int task = blockIdx.z, b = blockIdx.y;
    const int rc = blockIdx.x >> 1, cc = blockIdx.x & 1;
    const int t = threadIdx.x;

    // ---- stage this block's 1024 columns (2 pairs / thread), pre-scaled ----
    {
        const float* src; bool addm = false;
        if (task == 1)      { src = x  + (size_t)(b*2+0)*NPTS*3; addm = true; }  // PH
        else if (task == 2) { src = x  + (size_t)(b*2+0)*NPTS*3; }               // P0
        else if (task == 4) { src = y0 + (size_t)b*NPTS*3; }                     // Y
        else                { src = x  + (size_t)(b*2+1)*NPTS*3; }               // P1
#pragma unroll
        for (int k = 0; k < 2; k++) {
            int i = t + k * TPB;                       // local pair 0..511
            int gp = cc * NPAIR_BLK + i;               // global pair
            const float2* s2 = (const float2*)(src + (size_t)2 * gp * 3);
            float2 aa = s2[0], bb = s2[1], cc2 = s2[2];
            float px0 = aa.x, py0 = aa.y, pz0 = bb.x;
            float px1 = bb.y, py1 = cc2.x, pz1 = cc2.y;
            if (addm) {
                const float2* m2p = (const float2*)(mh + ((size_t)b*NPTS + 2*gp) * 3);
                float2 ma = m2p[0], mb2 = m2p[1], mc = m2p[2];
                px0 += ma.x;  py0 += ma.y;  pz0 += mb2.x;
                px1 += mb2.y; py1 += mc.x;  pz1 += mc.y;
            }
            float w0c = px0*px0 + py0*py0 + pz0*pz0;
            float w1c = px1*px1 + py1*py1 + pz1*pz1;
            sA[i] = make_ulonglong2(pack2(-2.f*px0, -2.f*px1), pack2(-2.f*py0, -2.f*py1));
            sB[i] = make_ulonglong2(pack2(-2.f*pz0, -2.f*pz1), pack2(w0c, w1c));
        }
    }

    // ---- this thread's 2 rows ----
    const int r0 = rc * ROWS_PER_BLK + t;
    const int r1 = r0 + TPB;
    float q0x, q0y, q0z, q1x, q1y, q1z;
    {
        const float* rsrc; bool addm = false;
        if (task == 0)      { rsrc = x  + (size_t)(b*2+0)*NPTS*3; addm = true; } // PH
        else if (task == 1) { rsrc = x  + (size_t)(b*2+1)*NPTS*3; }              // P1
        else if (task == 4) { rsrc = x  + (size_t)(b*2+0)*NPTS*3; }              // P0
        else                { rsrc = y0 + (size_t)b*NPTS*3; }                    // Y
        const float* s0 = rsrc + (size_t)r0 * 3;
        const float* s1 = rsrc + (size_t)r1 * 3;
        q0x = s0[0]; q0y = s0[1]; q0z = s0[2];
        q1x = s1[0]; q1y = s1[1]; q1z = s1[2];
        if (addm) {
            const float* m0 = mh + ((size_t)b*NPTS + r0) * 3;
            const float* m1 = mh + ((size_t)b*NPTS + r1) * 3;
            q0x += m0[0]; q0y += m0[1]; q0z += m0[2];
            q1x += m1[0]; q1y += m1[1]; q1z += m1[2];
        }
    }
    const float w0 = q0x*q0x + q0y*q0y + q0z*q0z;
    const float w1 = q1x*q1x + q1y*q1y + q1z*q1z;
    const u64 p0x2 = pack2(q0x, q0x), p0y2 = pack2(q0y, q0y), p0z2 = pack2(q0z, q0z);
    const u64 p1x2 = pack2(q1x, q1x), p1y2 = pack2(q1y, q1y), p1z2 = pack2(q1z, q1z);

    __syncthreads();

    const int base = b * NPTS;
    const int hslot = cc * BBN + base;

    if (task == 2) {
        float bA0 = 1e30f, bB0 = 1e30f, bA1 = 1e30f, bB1 = 1e30f;
        int   iA0 = 0, iB0 = 0, iA1 = 0, iB1 = 0;
#pragma unroll 4
        for (int j = 0; j < NPAIR_BLK; j++) {
            ulonglong2 xy = sA[j];
            ulonglong2 zw = sB[j];
            u64 a0 = fma2(xy.x, p0x2, fma2(xy.y, p0y2, fma2(zw.x, p0z2, zw.y)));
            u64 a1 = fma2(xy.x, p1x2, fma2(xy.y, p1y2, fma2(zw.x, p1z2, zw.y)));
            float l0, h0, l1, h1;
            unpack2(a0, l0, h0); unpack2(a1, l1, h1);
            bool c0 = l0 < bA0; iA0 = c0 ? j : iA0; bA0 = c0 ? l0 : bA0;
            bool c1 = h0 < bB0; iB0 = c1 ? j : iB0; bB0 = c1 ? h0 : bB0;
            bool c2 = l1 < bA1; iA1 = c2 ? j : iA1; bA1 = c2 ? l1 : bA1;
            bool c3 = h1 < bB1; iB1 = c3 ? j : iB1; bB1 = c3 ? h1 : bB1;
        }
        const int cbase = cc * COLS_PER_BLK;
        {
            float bst = bA0; int idx = 2*iA0;
            float bo  = bB0; int io  = 2*iB0 + 1;
            if (bo < bst || (bo == bst && io < idx)) { bst = bo; idx = io; }
            HD(2, cc, base + r0) = fmaxf(bst + w0, 0.f);
            g_hidx[hslot + r0]   = cbase + idx;
        }
        {
            float bst = bA1; int idx = 2*iA1;
            float bo  = bB1; int io  = 2*iB1 + 1;
            if (bo < bst || (bo == bst && io < idx)) { bst = bo; idx = io; }
            HD(2, cc, base + r1) = fmaxf(bst + w1, 0.f);
            g_hidx[hslot + r1]   = cbase + idx;
        }
    } else {
        float bA0 = 1e30f, bB0 = 1e30f, bA1 = 1e30f, bB1 = 1e30f;
#pragma unroll 8
        for (int j = 0; j < NPAIR_BLK; j++) {
            ulonglong2 xy = sA[j];
            ulonglong2 zw = sB[j];
            u64 a0 = fma2(xy.x, p0x2, fma2(xy.y, p0y2, fma2(zw.x, p0z2, zw.y)));
            u64 a1 = fma2(xy.x, p1x2, fma2(xy.y, p1y2, fma2(zw.x, p1z2, zw.y)));
            float l0, h0, l1, h1;
            unpack2(a0, l0, h0); unpack2(a1, l1, h1);
            bA0 = fminf(bA0, l0); bB0 = fminf(bB0, h0);
            bA1 = fminf(bA1, l1); bB1 = fminf(bB1, h1);
        }
        HD(task, cc, base + r0) = fmaxf(fminf(bA0, bB0) + w0, 0.f);
        HD(task, cc, base + r1) = fmaxf(fminf(bA1, bB1) + w1, 0.f);
    }
}

// ---------------- combine halves + scalar reductions ----------------
__global__ void k_reduce() {
    int i = blockIdx.x * blockDim.x + threadIdx.x;   // 0..8191
    int b = i >> 11;
    int lane = threadIdx.x & 31;

    float d1 = fminf(HD(0, 0, i), HD(0, 1, i));
    float d2 = fminf(HD(1, 0, i), HD(1, 1, i));

    // task2 combine: tie -> half 0 (lower global index = first occurrence)
    float m0 = HD(2, 0, i), m1v = HD(2, 1, i);
    int   i0 = g_hidx[i],   i1v = g_hidx[BBN + i];
    float m1; int id;
    if (m1v < m0) { m1 = m1v; id = i1v; } else { m1 = m0; id = i0; }
    g_min1[i] = m1;
    g_idx [i] = id;

    float m3 = fminf(HD(3, 0, i), HD(3, 1, i));
    g_min2[i] = fminf(m1, m3);     // min over concat [x_t0, x_t1]

    float c1 = fminf(HD(4, 0, i), HD(4, 1, i));
    float sv = (c1 < 0.1f) ? c1 : 0.f;
    float cv = (c1 < 0.1f) ? 1.f : 0.f;

    float ch = d1 + d2;
#pragma unroll
    for (int o = 16; o; o >>= 1) {
        ch += __shfl_xor_sync(0xffffffffu, ch, o);
        sv += __shfl_xor_sync(0xffffffffu, sv, o);
        cv += __shfl_xor_sync(0xffffffffu, cv, o);
    }
    if (lane == 0) {                   // whole warp shares one batch (32 | 2048)
        atomicAdd(&g_chamfer[b], ch);
        atomicAdd(&g_sumd, sv);
        atomicAdd(&g_cntd, (int)cv);
    }
}

// ---------------- losses ----------------
__global__ void k_final(const float* __restrict__ y0h, const float* __restrict__ y1h,
                        const float* __restrict__ mh) {
    int i = blockIdx.x * blockDim.x + threadIdx.x;   // 0..8191
    int b = i >> 11;
    float mc = ((g_chamfer[b] * (1.f / NPTS)) < 0.1f) ? 1.f : 0.f;
    float m1 = g_min1[i];
    int   id = g_idx[i];
    float m2 = g_min2[i];
    float md = (sqrtf(m1) < 0.05f) ? 1.f : 0.f;
    float mn = (sqrtf(m2) > 0.2f) ? 1.f : 0.f;
    float cmd = mc * md;
    float ldyn = 0.f, lsta = 0.f;
#pragma unroll
    for (int k = 0; k < 3; k++) {
        float dy = y1h[(size_t)i*3 + k] - y0h[(size_t)i*3 + k];
        float nm = mh[((size_t)b*NPTS + id)*3 + k];
        float e  = (dy - nm) * cmd;
        ldyn = fmaf(e, e, ldyn);
        float ss = dy * mn;
        lsta = fmaf(ss, ss, lsta);
    }
#pragma unroll
    for (int o = 16; o; o >>= 1) {
        ldyn += __shfl_xor_sync(0xffffffffu, ldyn, o);
        lsta += __shfl_xor_sync(0xffffffffu, lsta, o);
    }
    __shared__ float sd[8], ss2[8];
    int warp = threadIdx.x >> 5, lane = threadIdx.x & 31;
    if (lane == 0) { sd[warp] = ldyn; ss2[warp] = lsta; }
    __syncthreads();
    if (threadIdx.x == 0) {
        float a = 0.f, c = 0.f;
#pragma unroll
        for (int w = 0; w < 8; w++) { a += sd[w]; c += ss2[w]; }
        atomicAdd(&g_dyn, a);
        atomicAdd(&g_stat, c);
    }
}

// ---------------- writeout + accumulator reset (replay-safe) ---------------
__global__ void k_write(float* __restrict__ out) {
    const float inv = 1.f / (float)(BB * NPTS * 3);
    out[0] = g_dyn  * inv;
    out[1] = g_stat * inv;
    out[2] = g_sumd / fmaxf((float)g_cntd, 1.f);
    g_chamfer[0] = g_chamfer[1] = g_chamfer[2] = g_chamfer[3] = 0.f;
    g_sumd = 0.f; g_cntd = 0; g_dyn = 0.f; g_stat = 0.f;
}

// ---------------- launch: 4 kernels ----------------
extern "C" void kernel_launch(void* const* d_in, const int* in_sizes, int n_in,
                              void* d_out, int out_size) {
    const float* x   = (const float*)d_in[0];  // (B,2,N,3)
    const float* mh  = (const float*)d_in[1];  // (B,1,N,3)
    const float* y0h = (const float*)d_in[2];  // (B,1,M,3)
    const float* y1h = (const float*)d_in[3];  // (B,1,M,3)
    float* out = (float*)d_out;

    k_pair  <<<dim3(RC * CC, BB, 5), TPB>>>(x, mh, y0h);
    k_reduce<<<BBN / 256, 256>>>();
    k_final <<<BBN / 256, 256>>>(y0h, y1h, mh);
    k_write <<<1, 1>>>(out);
}

// round 7
// speedup vs baseline: 1.7951x; 1.0553x over previous
#include <cuda_runtime.h>

#define BB    4
#define NPTS  2048
#define BBN   (BB * NPTS)
#define TPB   256
#define RC    4                      // row chunks
#define CC    2                      // column halves
#define RCCC  (RC * CC)              // 8 x-blocks
#define NBLK  (RCCC * BB * 5)        // 160 total blocks
#define NEPI  (RCCC * BB)            // 32 epilogue (task-0) blocks
#define ROWS_PER_BLK (NPTS / RC)     // 512 = 2 * TPB
#define COLS_PER_BLK (NPTS / CC)     // 1024
#define NPAIR_BLK (COLS_PER_BLK / 2) // 512 pairs staged

typedef unsigned long long u64;
typedef unsigned int       u32;

// ---------------- device scratch (plain stores, single writer per slot) ----
__device__ float g_hd[5 * CC * BBN];     // [task][half][row] half row-mins
__device__ int   g_hidx[CC * BBN];       // task2 half argmins (global col idx)
// accumulators + barriers: zero at load, reset by writeout thread each replay
__device__ float g_chamfer[BB];
__device__ float g_dynb[BB];
__device__ float g_stat;
__device__ float g_sumd;
__device__ int   g_cntd;
__device__ int   g_bar1, g_bar2;

#define HD(task, half, i) g_hd[((task) * CC + (half)) * BBN + (i)]

// ---------------- f32x2 helpers ----------------
__device__ __forceinline__ u64 pack2(float lo, float hi) {
    u64 r; asm("mov.b64 %0, {%1,%2};" : "=l"(r) : "f"(lo), "f"(hi)); return r;
}
__device__ __forceinline__ void unpack2(u64 v, float& lo, float& hi) {
    asm("mov.b64 {%0,%1}, %2;" : "=f"(lo), "=f"(hi) : "l"(v));
}
__device__ __forceinline__ u64 fma2(u64 a, u64 b, u64 c) {
    u64 d; asm("fma.rn.f32x2 %0, %1, %2, %3;" : "=l"(d) : "l"(a), "l"(b), "l"(c)); return d;
}

// ---------------- single fused kernel ----------------
// task 0: rows PH, cols P1   task 1: rows P1, cols PH
// task 2: rows Y,  cols P0 (argmin)   task 3: rows Y, cols P1
// task 4: rows P0, cols Y
__global__ void __launch_bounds__(TPB, 2) k_all(const float* __restrict__ x,
                                                const float* __restrict__ mh,
                                                const float* __restrict__ y0h,
                                                const float* __restrict__ y1h,
                                                float* __restrict__ out) {
    __shared__ ulonglong2 sA[NPAIR_BLK];   // (x0,x1),(y0,y1) scaled by -2
    __shared__ ulonglong2 sB[NPAIR_BLK];   // (z0,z1),(w0,w1) w=|q|^2
    const int task = blockIdx.z, b = blockIdx.y;
    const int rc = blockIdx.x >> 1, cc = blockIdx.x & 1;
    const int t = threadIdx.x;
    const float* y0 = y0h;

    // ======== phase 0: pairwise chunk ========
    {
        const float* src; bool addm = false;
        if (task == 1)      { src = x  + (size_t)(b*2+0)*NPTS*3; addm = true; }  // PH
        else if (task == 2) { src = x  + (size_t)(b*2+0)*NPTS*3; }               // P0
        else if (task == 4) { src = y0 + (size_t)b*NPTS*3; }                     // Y
        else                { src = x  + (size_t)(b*2+1)*NPTS*3; }               // P1
#pragma unroll
        for (int k = 0; k < 2; k++) {
            int i = t + k * TPB;                       // local pair 0..511
            int gp = cc * NPAIR_BLK + i;               // global pair
            const float2* s2 = (const float2*)(src + (size_t)2 * gp * 3);
            float2 aa = s2[0], bb = s2[1], cc2 = s2[2];
            float px0 = aa.x, py0 = aa.y, pz0 = bb.x;
            float px1 = bb.y, py1 = cc2.x, pz1 = cc2.y;
            if (addm) {
                const float2* m2p = (const float2*)(mh + ((size_t)b*NPTS + 2*gp) * 3);
                float2 ma = m2p[0], mb2 = m2p[1], mc = m2p[2];
                px0 += ma.x;  py0 += ma.y;  pz0 += mb2.x;
                px1 += mb2.y; py1 += mc.x;  pz1 += mc.y;
            }
            float w0c = px0*px0 + py0*py0 + pz0*pz0;
            float w1c = px1*px1 + py1*py1 + pz1*pz1;
            sA[i] = make_ulonglong2(pack2(-2.f*px0, -2.f*px1), pack2(-2.f*py0, -2.f*py1));
            sB[i] = make_ulonglong2(pack2(-2.f*pz0, -2.f*pz1), pack2(w0c, w1c));
        }
    }

    const int r0 = rc * ROWS_PER_BLK + t;
    const int r1 = r0 + TPB;
    float q0x, q0y, q0z, q1x, q1y, q1z;
    {
        const float* rsrc; bool addm = false;
        if (task == 0)      { rsrc = x  + (size_t)(b*2+0)*NPTS*3; addm = true; } // PH
        else if (task == 1) { rsrc = x  + (size_t)(b*2+1)*NPTS*3; }              // P1
        else if (task == 4) { rsrc = x  + (size_t)(b*2+0)*NPTS*3; }              // P0
        else                { rsrc = y0 + (size_t)b*NPTS*3; }                    // Y
        const float* s0 = rsrc + (size_t)r0 * 3;
        const float* s1 = rsrc + (size_t)r1 * 3;
        q0x = s0[0]; q0y = s0[1]; q0z = s0[2];
        q1x = s1[0]; q1y = s1[1]; q1z = s1[2];
        if (addm) {
            const float* m0 = mh + ((size_t)b*NPTS + r0) * 3;
            const float* m1 = mh + ((size_t)b*NPTS + r1) * 3;
            q0x += m0[0]; q0y += m0[1]; q0z += m0[2];
            q1x += m1[0]; q1y += m1[1]; q1z += m1[2];
        }
    }
    const float w0 = q0x*q0x + q0y*q0y + q0z*q0z;
    const float w1 = q1x*q1x + q1y*q1y + q1z*q1z;
    const u64 p0x2 = pack2(q0x, q0x), p0y2 = pack2(q0y, q0y), p0z2 = pack2(q0z, q0z);
    const u64 p1x2 = pack2(q1x, q1x), p1y2 = pack2(q1y, q1y), p1z2 = pack2(q1z, q1z);

    __syncthreads();

    const int base = b * NPTS;

    if (task == 2) {
        float bA0 = 1e30f, bB0 = 1e30f, bA1 = 1e30f, bB1 = 1e30f;
        int   iA0 = 0, iB0 = 0, iA1 = 0, iB1 = 0;
#pragma unroll 4
        for (int j = 0; j < NPAIR_BLK; j++) {
            ulonglong2 xy = sA[j];
            ulonglong2 zw = sB[j];
            u64 a0 = fma2(xy.x, p0x2, fma2(xy.y, p0y2, fma2(zw.x, p0z2, zw.y)));
            u64 a1 = fma2(xy.x, p1x2, fma2(xy.y, p1y2, fma2(zw.x, p1z2, zw.y)));
            float l0, h0, l1, h1;
            unpack2(a0, l0, h0); unpack2(a1, l1, h1);
            bool c0 = l0 < bA0; iA0 = c0 ? j : iA0; bA0 = c0 ? l0 : bA0;
            bool c1 = h0 < bB0; iB0 = c1 ? j : iB0; bB0 = c1 ? h0 : bB0;
            bool c2 = l1 < bA1; iA1 = c2 ? j : iA1; bA1 = c2 ? l1 : bA1;
            bool c3 = h1 < bB1; iB1 = c3 ? j : iB1; bB1 = c3 ? h1 : bB1;
        }
        const int cbase = cc * COLS_PER_BLK;
        const int hslot = cc * BBN + base;
        {
            float bst = bA0; int idx = 2*iA0;
            float bo  = bB0; int io  = 2*iB0 + 1;
            if (bo < bst || (bo == bst && io < idx)) { bst = bo; idx = io; }
            HD(2, cc, base + r0) = fmaxf(bst + w0, 0.f);
            g_hidx[hslot + r0]   = cbase + idx;
        }
        {
            float bst = bA1; int idx = 2*iA1;
            float bo  = bB1; int io  = 2*iB1 + 1;
            if (bo < bst || (bo == bst && io < idx)) { bst = bo; idx = io; }
            HD(2, cc, base + r1) = fmaxf(bst + w1, 0.f);
            g_hidx[hslot + r1]   = cbase + idx;
        }
    } else {
        float bA0 = 1e30f, bB0 = 1e30f, bA1 = 1e30f, bB1 = 1e30f;
#pragma unroll 8
        for (int j = 0; j < NPAIR_BLK; j++) {
            ulonglong2 xy = sA[j];
            ulonglong2 zw = sB[j];
            u64 a0 = fma2(xy.x, p0x2, fma2(xy.y, p0y2, fma2(zw.x, p0z2, zw.y)));
            u64 a1 = fma2(xy.x, p1x2, fma2(xy.y, p1y2, fma2(zw.x, p1z2, zw.y)));
            float l0, h0, l1, h1;
            unpack2(a0, l0, h0); unpack2(a1, l1, h1);
            bA0 = fminf(bA0, l0); bB0 = fminf(bB0, h0);
            bA1 = fminf(bA1, l1); bB1 = fminf(bB1, h1);
        }
        HD(task, cc, base + r0) = fmaxf(fminf(bA0, bB0) + w0, 0.f);
        HD(task, cc, base + r1) = fmaxf(fminf(bA1, bB1) + w1, 0.f);
    }

    // ======== barrier 1: all 160 blocks' stores visible ========
    __threadfence();
    __syncthreads();
    if (t == 0) atomicAdd(&g_bar1, 1);

    if (task != 0) return;                 // only 32 task-0 blocks continue

    if (t == 0) {
        volatile int* p = &g_bar1;
        while (*p < NBLK) { }
    }
    __syncthreads();
    __threadfence();

    // ======== phase 1: per-row epilogue across 32 blocks x 256 thr ========
    {
        const int wid = b * RCCC + blockIdx.x;    // 0..31
        const int i = wid * TPB + t;              // row 0..8191
        const int ib = i >> 11;                   // batch of this row
        float d1 = fminf(HD(0, 0, i), HD(0, 1, i));
        float d2 = fminf(HD(1, 0, i), HD(1, 1, i));
        float m0 = HD(2, 0, i), m1v = HD(2, 1, i);
        int   i0 = g_hidx[i],   i1v = g_hidx[BBN + i];
        float m1; int id;
        if (m1v < m0) { m1 = m1v; id = i1v; } else { m1 = m0; id = i0; }
        float m3 = fminf(HD(3, 0, i), HD(3, 1, i));
        float m2 = fminf(m1, m3);
        float c1 = fminf(HD(4, 0, i), HD(4, 1, i));

        float md = (sqrtf(m1) < 0.05f) ? 1.f : 0.f;
        float mn = (sqrtf(m2) > 0.2f)  ? 1.f : 0.f;
        float sv = (c1 < 0.1f) ? c1 : 0.f;
        float cv = (c1 < 0.1f) ? 1.f : 0.f;

        float pdyn = 0.f, psta = 0.f;
#pragma unroll
        for (int k = 0; k < 3; k++) {
            float dy = y1h[(size_t)i*3 + k] - y0h[(size_t)i*3 + k];
            float nm = mh[((size_t)ib*NPTS + id)*3 + k];
            float e  = dy - nm;
            pdyn = fmaf(e, e, pdyn);
            float ss = dy * mn;
            psta = fmaf(ss, ss, psta);
        }
        pdyn *= md;                      // mc applied per-batch at writeout

        float ch = d1 + d2;
#pragma unroll
        for (int o = 16; o; o >>= 1) {
            ch   += __shfl_xor_sync(0xffffffffu, ch,   o);
            sv   += __shfl_xor_sync(0xffffffffu, sv,   o);
            cv   += __shfl_xor_sync(0xffffffffu, cv,   o);
            pdyn += __shfl_xor_sync(0xffffffffu, pdyn, o);
            psta += __shfl_xor_sync(0xffffffffu, psta, o);
        }
        if ((t & 31) == 0) {             // warp spans one batch (32 | 2048)
            atomicAdd(&g_chamfer[ib], ch);
            atomicAdd(&g_dynb[ib], pdyn);
            atomicAdd(&g_stat, psta);
            atomicAdd(&g_sumd, sv);
            atomicAdd(&g_cntd, (int)cv);
        }
    }

    // ======== barrier 2 + writeout (one thread) ========
    __threadfence();
    __syncthreads();
    if (t == 0) atomicAdd(&g_bar2, 1);

    if (b == 0 && blockIdx.x == 0 && t == 0) {
        volatile int* p = &g_bar2;
        while (*p < NEPI) { }
        __threadfence();
        const float inv = 1.f / (float)(BB * NPTS * 3);
        float dyn = 0.f;
#pragma unroll
        for (int bb = 0; bb < BB; bb++) {
            float mc = ((g_chamfer[bb] * (1.f / NPTS)) < 0.1f) ? 1.f : 0.f;
            dyn += mc * g_dynb[bb];
        }
        out[0] = dyn * inv;
        out[1] = g_stat * inv;
        out[2] = g_sumd / fmaxf((float)g_cntd, 1.f);
        // reset for next graph replay
#pragma unroll
        for (int bb = 0; bb < BB; bb++) { g_chamfer[bb] = 0.f; g_dynb[bb] = 0.f; }
        g_stat = 0.f; g_sumd = 0.f; g_cntd = 0;
        g_bar1 = 0; g_bar2 = 0;
    }
}

// ---------------- launch: ONE kernel ----------------
extern "C" void kernel_launch(void* const* d_in, const int* in_sizes, int n_in,
                              void* d_out, int out_size) {
    const float* x   = (const float*)d_in[0];  // (B,2,N,3)
    const float* mh  = (const float*)d_in[1];  // (B,1,N,3)
    const float* y0h = (const float*)d_in[2];  // (B,1,M,3)
    const float* y1h = (const float*)d_in[3];  // (B,1,M,3)
    float* out = (float*)d_out;

    k_all<<<dim3(RCCC, BB, 5), TPB>>>(x, mh, y0h, y1h, out);
}

// round 9
// speedup vs baseline: 1.9043x; 1.0609x over previous
#include <cuda_runtime.h>

#define BB    4
#define NPTS  2048
#define BBN   (BB * NPTS)
#define TPB   256
#define RC    4                      // row chunks
#define CC    4                      // column quarters
#define RCCC  (RC * CC)              // 16 x-blocks
#define NBLK  (RCCC * BB * 5)        // 320 total blocks
#define NEPI  (RCCC * BB)            // 64 epilogue (task-0) blocks
#define EPI_ROWS (BBN / NEPI)        // 128 rows per epilogue block
#define ROWS_PER_BLK (NPTS / RC)     // 512 = 2 * TPB
#define COLS_PER_BLK (NPTS / CC)     // 512
#define NPAIR_BLK (COLS_PER_BLK / 2) // 256 pairs staged

typedef unsigned long long u64;
typedef unsigned int       u32;

// ---------------- device scratch (plain stores, single writer per slot) ----
__device__ float g_hd[5 * CC * BBN];     // [task][quarter][row] partial row-mins
__device__ int   g_hidx[CC * BBN];       // task2 quarter argmins (global col idx)
// accumulators + barriers: zero at load, reset by writeout thread each replay
__device__ float g_chamfer[BB];
__device__ float g_dynb[BB];
__device__ float g_stat;
__device__ float g_sumd;
__device__ int   g_cntd;
__device__ int   g_bar1, g_bar2;

#define HD(task, q, i) g_hd[((task) * CC + (q)) * BBN + (i)]

// ---------------- f32x2 helpers ----------------
__device__ __forceinline__ u64 pack2(float lo, float hi) {
    u64 r; asm("mov.b64 %0, {%1,%2};" : "=l"(r) : "f"(lo), "f"(hi)); return r;
}
__device__ __forceinline__ void unpack2(u64 v, float& lo, float& hi) {
    asm("mov.b64 {%0,%1}, %2;" : "=f"(lo), "=f"(hi) : "l"(v));
}
__device__ __forceinline__ u64 fma2(u64 a, u64 b, u64 c) {
    u64 d; asm("fma.rn.f32x2 %0, %1, %2, %3;" : "=l"(d) : "l"(a), "l"(b), "l"(c)); return d;
}

// ---------------- single fused kernel ----------------
// task 0: rows PH, cols P1   task 1: rows P1, cols PH
// task 2: rows Y,  cols P0 (argmin)   task 3: rows Y, cols P1
// task 4: rows P0, cols Y
__global__ void __launch_bounds__(TPB, 3) k_all(const float* __restrict__ x,
                                                const float* __restrict__ mh,
                                                const float* __restrict__ y0h,
                                                const float* __restrict__ y1h,
                                                float* __restrict__ out) {
    __shared__ ulonglong2 sA[NPAIR_BLK];   // (x0,x1),(y0,y1) scaled by -2
    __shared__ ulonglong2 sB[NPAIR_BLK];   // (z0,z1),(w0,w1) w=|q|^2
    const int task = blockIdx.z, b = blockIdx.y;
    const int rc = blockIdx.x >> 2, cc = blockIdx.x & 3;
    const int t = threadIdx.x;
    const float* y0 = y0h;

    // ======== phase 0: stage this block's 512 columns (1 pair/thread) ========
    {
        const float* src; bool addm = false;
        if (task == 1)      { src = x  + (size_t)(b*2+0)*NPTS*3; addm = true; }  // PH
        else if (task == 2) { src = x  + (size_t)(b*2+0)*NPTS*3; }               // P0
        else if (task == 4) { src = y0 + (size_t)b*NPTS*3; }                     // Y
        else                { src = x  + (size_t)(b*2+1)*NPTS*3; }               // P1
        int gp = cc * NPAIR_BLK + t;                   // global pair
        const float2* s2 = (const float2*)(src + (size_t)2 * gp * 3);
        float2 aa = s2[0], bb = s2[1], cc2 = s2[2];
        float px0 = aa.x, py0 = aa.y, pz0 = bb.x;
        float px1 = bb.y, py1 = cc2.x, pz1 = cc2.y;
        if (addm) {
            const float2* m2p = (const float2*)(mh + ((size_t)b*NPTS + 2*gp) * 3);
            float2 ma = m2p[0], mb2 = m2p[1], mc = m2p[2];
            px0 += ma.x;  py0 += ma.y;  pz0 += mb2.x;
            px1 += mb2.y; py1 += mc.x;  pz1 += mc.y;
        }
        float w0c = px0*px0 + py0*py0 + pz0*pz0;
        float w1c = px1*px1 + py1*py1 + pz1*pz1;
        sA[t] = make_ulonglong2(pack2(-2.f*px0, -2.f*px1), pack2(-2.f*py0, -2.f*py1));
        sB[t] = make_ulonglong2(pack2(-2.f*pz0, -2.f*pz1), pack2(w0c, w1c));
    }

    // ---- this thread's 2 rows ----
    const int r0 = rc * ROWS_PER_BLK + t;
    const int r1 = r0 + TPB;
    float q0x, q0y, q0z, q1x, q1y, q1z;
    {
        const float* rsrc; bool addm = false;
        if (task == 0)      { rsrc = x  + (size_t)(b*2+0)*NPTS*3; addm = true; } // PH
        else if (task == 1) { rsrc = x  + (size_t)(b*2+1)*NPTS*3; }              // P1
        else if (task == 4) { rsrc = x  + (size_t)(b*2+0)*NPTS*3; }              // P0
        else                { rsrc = y0 + (size_t)b*NPTS*3; }                    // Y
        const float* s0 = rsrc + (size_t)r0 * 3;
        const float* s1 = rsrc + (size_t)r1 * 3;
        q0x = s0[0]; q0y = s0[1]; q0z = s0[2];
        q1x = s1[0]; q1y = s1[1]; q1z = s1[2];
        if (addm) {
            const float* m0 = mh + ((size_t)b*NPTS + r0) * 3;
            const float* m1 = mh + ((size_t)b*NPTS + r1) * 3;
            q0x += m0[0]; q0y += m0[1]; q0z += m0[2];
            q1x += m1[0]; q1y += m1[1]; q1z += m1[2];
        }
    }
    const float w0 = q0x*q0x + q0y*q0y + q0z*q0z;
    const float w1 = q1x*q1x + q1y*q1y + q1z*q1z;
    const u64 p0x2 = pack2(q0x, q0x), p0y2 = pack2(q0y, q0y), p0z2 = pack2(q0z, q0z);
    const u64 p1x2 = pack2(q1x, q1x), p1y2 = pack2(q1y, q1y), p1z2 = pack2(q1z, q1z);

    __syncthreads();

    const int base = b * NPTS;

    if (task == 2) {
        float bA0 = 1e30f, bB0 = 1e30f, bA1 = 1e30f, bB1 = 1e30f;
        int   iA0 = 0, iB0 = 0, iA1 = 0, iB1 = 0;
#pragma unroll 4
        for (int j = 0; j < NPAIR_BLK; j++) {
            ulonglong2 xy = sA[j];
            ulonglong2 zw = sB[j];
            u64 a0 = fma2(xy.x, p0x2, fma2(xy.y, p0y2, fma2(zw.x, p0z2, zw.y)));
            u64 a1 = fma2(xy.x, p1x2, fma2(xy.y, p1y2, fma2(zw.x, p1z2, zw.y)));
            float l0, h0, l1, h1;
            unpack2(a0, l0, h0); unpack2(a1, l1, h1);
            bool c0 = l0 < bA0; iA0 = c0 ? j : iA0; bA0 = c0 ? l0 : bA0;
            bool c1 = h0 < bB0; iB0 = c1 ? j : iB0; bB0 = c1 ? h0 : bB0;
            bool c2 = l1 < bA1; iA1 = c2 ? j : iA1; bA1 = c2 ? l1 : bA1;
            bool c3 = h1 < bB1; iB1 = c3 ? j : iB1; bB1 = c3 ? h1 : bB1;
        }
        const int cbase = cc * COLS_PER_BLK;
        const int hslot = cc * BBN + base;
        {
            float bst = bA0; int idx = 2*iA0;
            float bo  = bB0; int io  = 2*iB0 + 1;
            if (bo < bst || (bo == bst && io < idx)) { bst = bo; idx = io; }
            HD(2, cc, base + r0) = fmaxf(bst + w0, 0.f);
            g_hidx[hslot + r0]   = cbase + idx;
        }
        {
            float bst = bA1; int idx = 2*iA1;
            float bo  = bB1; int io  = 2*iB1 + 1;
            if (bo < bst || (bo == bst && io < idx)) { bst = bo; idx = io; }
            HD(2, cc, base + r1) = fmaxf(bst + w1, 0.f);
            g_hidx[hslot + r1]   = cbase + idx;
        }
    } else {
        float bA0 = 1e30f, bB0 = 1e30f, bA1 = 1e30f, bB1 = 1e30f;
#pragma unroll 8
        for (int j = 0; j < NPAIR_BLK; j++) {
            ulonglong2 xy = sA[j];
            ulonglong2 zw = sB[j];
            u64 a0 = fma2(xy.x, p0x2, fma2(xy.y, p0y2, fma2(zw.x, p0z2, zw.y)));
            u64 a1 = fma2(xy.x, p1x2, fma2(xy.y, p1y2, fma2(zw.x, p1z2, zw.y)));
            float l0, h0, l1, h1;
            unpack2(a0, l0, h0); unpack2(a1, l1, h1);
            bA0 = fminf(bA0, l0); bB0 = fminf(bB0, h0);
            bA1 = fminf(bA1, l1); bB1 = fminf(bB1, h1);
        }
        HD(task, cc, base + r0) = fmaxf(fminf(bA0, bB0) + w0, 0.f);
        HD(task, cc, base + r1) = fmaxf(fminf(bA1, bB1) + w1, 0.f);
    }

    // ======== barrier 1: all 320 blocks' stores visible ========
    __threadfence();
    __syncthreads();
    if (t == 0) atomicAdd(&g_bar1, 1);

    if (task != 0) return;                 // only 64 task-0 blocks continue

    if (t == 0) {
        volatile int* p = &g_bar1;
        while (*p < NBLK) { }
    }
    __syncthreads();
    __threadfence();

    // ======== phase 1: per-row epilogue (64 blocks x first 128 threads) ====
    {
        const int wid = b * RCCC + blockIdx.x;    // 0..63
        float ch = 0.f, sv = 0.f, cv = 0.f, pdyn = 0.f, psta = 0.f;
        int ib = 0;
        if (t < EPI_ROWS) {
            const int i = wid * EPI_ROWS + t;     // row 0..8191
            ib = i >> 11;
            float d1 = fminf(fminf(HD(0,0,i), HD(0,1,i)), fminf(HD(0,2,i), HD(0,3,i)));
            float d2 = fminf(fminf(HD(1,0,i), HD(1,1,i)), fminf(HD(1,2,i), HD(1,3,i)));
            // argmin combine: ascending quarter order, strict < keeps lowest idx
            float m1 = HD(2, 0, i); int id = g_hidx[i];
#pragma unroll
            for (int q = 1; q < CC; q++) {
                float mq = HD(2, q, i);
                int   iq = g_hidx[q * BBN + i];
                if (mq < m1) { m1 = mq; id = iq; }
            }
            float m3 = fminf(fminf(HD(3,0,i), HD(3,1,i)), fminf(HD(3,2,i), HD(3,3,i)));
            float m2 = fminf(m1, m3);
            float c1 = fminf(fminf(HD(4,0,i), HD(4,1,i)), fminf(HD(4,2,i), HD(4,3,i)));

            float md = (sqrtf(m1) < 0.05f) ? 1.f : 0.f;
            float mn = (sqrtf(m2) > 0.2f)  ? 1.f : 0.f;
            sv = (c1 < 0.1f) ? c1 : 0.f;
            cv = (c1 < 0.1f) ? 1.f : 0.f;
            ch = d1 + d2;

#pragma unroll
            for (int k = 0; k < 3; k++) {
                float dy = y1h[(size_t)i*3 + k] - y0h[(size_t)i*3 + k];
                float nm = mh[((size_t)ib*NPTS + id)*3 + k];
                float e  = dy - nm;
                pdyn = fmaf(e, e, pdyn);
                float ss = dy * mn;
                psta = fmaf(ss, ss, psta);
            }
            pdyn *= md;                    // mc applied per-batch at writeout
        }
#pragma unroll
        for (int o = 16; o; o >>= 1) {
            ch   += __shfl_xor_sync(0xffffffffu, ch,   o);
            sv   += __shfl_xor_sync(0xffffffffu, sv,   o);
            cv   += __shfl_xor_sync(0xffffffffu, cv,   o);
            pdyn += __shfl_xor_sync(0xffffffffu, pdyn, o);
            psta += __shfl_xor_sync(0xffffffffu, psta, o);
        }
        ib = __shfl_sync(0xffffffffu, ib, 0);   // batch uniform per warp (32 | 128-row span)
        if ((t & 31) == 0 && t < EPI_ROWS) {
            atomicAdd(&g_chamfer[ib], ch);
            atomicAdd(&g_dynb[ib], pdyn);
            atomicAdd(&g_stat, psta);
            atomicAdd(&g_sumd, sv);
            atomicAdd(&g_cntd, (int)cv);
        }
    }

    // ======== barrier 2 + writeout (one thread) ========
    __threadfence();
    __syncthreads();
    if (t == 0) atomicAdd(&g_bar2, 1);

    if (b == 0 && blockIdx.x == 0 && t == 0) {
        volatile int* p = &g_bar2;
        while (*p < NEPI) { }
        __threadfence();
        const float inv = 1.f / (float)(BB * NPTS * 3);
        float dyn = 0.f;
#pragma unroll
        for (int bb = 0; bb < BB; bb++) {
            float mc = ((g_chamfer[bb] * (1.f / NPTS)) < 0.1f) ? 1.f : 0.f;
            dyn += mc * g_dynb[bb];
        }
        out[0] = dyn * inv;
        out[1] = g_stat * inv;
        out[2] = g_sumd / fmaxf((float)g_cntd, 1.f);
        // reset for next graph replay
#pragma unroll
        for (int bb = 0; bb < BB; bb++) { g_chamfer[bb] = 0.f; g_dynb[bb] = 0.f; }
        g_stat = 0.f; g_sumd = 0.f; g_cntd = 0;
        g_bar1 = 0; g_bar2 = 0;
    }
}

// ---------------- launch: ONE kernel ----------------
extern "C" void kernel_launch(void* const* d_in, const int* in_sizes, int n_in,
                              void* d_out, int out_size) {
    const float* x   = (const float*)d_in[0];  // (B,2,N,3)
    const float* mh  = (const float*)d_in[1];  // (B,1,N,3)
    const float* y0h = (const float*)d_in[2];  // (B,1,M,3)
    const float* y1h = (const float*)d_in[3];  // (B,1,M,3)
    float* out = (float*)d_out;

    k_all<<<dim3(RCCC, BB, 5), TPB>>>(x, mh, y0h, y1h, out);
}

// round 10
// speedup vs baseline: 1.9232x; 1.0099x over previous
#include <cuda_runtime.h>

#define BB    4
#define NPTS  2048
#define BBN   (BB * NPTS)
#define TPB   256
#define RC    4                      // row chunks (512 rows each)
#define CC    16                     // column chunks (128 cols each)
#define NTILE (5 * BB * RC * CC)     // 1280 tiles
#define NBLK1 444                    // K1 blocks (3 per SM)
#define ROWS_PER_TILE (NPTS / RC)    // 512 = 2 * TPB
#define COLS_PER_TILE (NPTS / CC)    // 128
#define NPAIR_TILE (COLS_PER_TILE/2) // 64 pairs staged
#define NBLK2 64                     // K2 blocks
#define TPB2  128

typedef unsigned long long u64;
typedef unsigned int       u32;

// ---------------- device scratch (plain stores, single writer per slot) ----
__device__ float g_hd[5 * CC * BBN];     // [task][chunk][row] partial row-mins
__device__ int   g_hidx[CC * BBN];       // task2 chunk argmins (global col idx)
// accumulators: zero at load, reset by last epilogue block each replay
__device__ float g_chamfer[BB];
__device__ float g_dynb[BB];
__device__ float g_stat;
__device__ float g_sumd;
__device__ int   g_cntd;
__device__ int   g_done;

#define HD(task, q, i) g_hd[((task) * CC + (q)) * BBN + (i)]

// ---------------- f32x2 helpers ----------------
__device__ __forceinline__ u64 pack2(float lo, float hi) {
    u64 r; asm("mov.b64 %0, {%1,%2};" : "=l"(r) : "f"(lo), "f"(hi)); return r;
}
__device__ __forceinline__ void unpack2(u64 v, float& lo, float& hi) {
    asm("mov.b64 {%0,%1}, %2;" : "=f"(lo), "=f"(hi) : "l"(v));
}
__device__ __forceinline__ u64 fma2(u64 a, u64 b, u64 c) {
    u64 d; asm("fma.rn.f32x2 %0, %1, %2, %3;" : "=l"(d) : "l"(a), "l"(b), "l"(c)); return d;
}

// ---------------- K1: pairwise over fine tiles ----------------
// task 0: rows PH, cols P1   task 1: rows P1, cols PH
// task 2: rows Y,  cols P0 (argmin)   task 3: rows Y, cols P1
// task 4: rows P0, cols Y
__global__ void __launch_bounds__(TPB, 3) k_pair(const float* __restrict__ x,
                                                 const float* __restrict__ mh,
                                                 const float* __restrict__ y0) {
    __shared__ ulonglong2 sA[NPAIR_TILE];   // (x0,x1),(y0,y1) scaled by -2
    __shared__ ulonglong2 sB[NPAIR_TILE];   // (z0,z1),(w0,w1) w=|q|^2
    const int t = threadIdx.x;

    for (int tau = blockIdx.x; tau < NTILE; tau += NBLK1) {
        const int task = tau >> 8;             // / 256
        const int rem  = tau & 255;
        const int b    = rem >> 6;             // / 64
        const int rc   = (rem >> 4) & 3;
        const int cc   = rem & 15;

        // ---- stage 128 columns (64 pairs), pre-scaled ----
        __syncthreads();                       // protect smem from previous tile
        if (t < NPAIR_TILE) {
            const float* src; bool addm = false;
            if (task == 1)      { src = x  + (size_t)(b*2+0)*NPTS*3; addm = true; }  // PH
            else if (task == 2) { src = x  + (size_t)(b*2+0)*NPTS*3; }               // P0
            else if (task == 4) { src = y0 + (size_t)b*NPTS*3; }                     // Y
            else                { src = x  + (size_t)(b*2+1)*NPTS*3; }               // P1
            int gp = cc * NPAIR_TILE + t;
            const float2* s2 = (const float2*)(src + (size_t)2 * gp * 3);
            float2 aa = s2[0], bb = s2[1], cc2 = s2[2];
            float px0 = aa.x, py0 = aa.y, pz0 = bb.x;
            float px1 = bb.y, py1 = cc2.x, pz1 = cc2.y;
            if (addm) {
                const float2* m2p = (const float2*)(mh + ((size_t)b*NPTS + 2*gp) * 3);
                float2 ma = m2p[0], mb2 = m2p[1], mc = m2p[2];
                px0 += ma.x;  py0 += ma.y;  pz0 += mb2.x;
                px1 += mb2.y; py1 += mc.x;  pz1 += mc.y;
            }
            float w0c = px0*px0 + py0*py0 + pz0*pz0;
            float w1c = px1*px1 + py1*py1 + pz1*pz1;
            sA[t] = make_ulonglong2(pack2(-2.f*px0, -2.f*px1), pack2(-2.f*py0, -2.f*py1));
            sB[t] = make_ulonglong2(pack2(-2.f*pz0, -2.f*pz1), pack2(w0c, w1c));
        }

        // ---- this thread's 2 rows ----
        const int r0 = rc * ROWS_PER_TILE + t;
        const int r1 = r0 + TPB;
        float q0x, q0y, q0z, q1x, q1y, q1z;
        {
            const float* rsrc; bool addm = false;
            if (task == 0)      { rsrc = x  + (size_t)(b*2+0)*NPTS*3; addm = true; } // PH
            else if (task == 1) { rsrc = x  + (size_t)(b*2+1)*NPTS*3; }              // P1
            else if (task == 4) { rsrc = x  + (size_t)(b*2+0)*NPTS*3; }              // P0
            else                { rsrc = y0 + (size_t)b*NPTS*3; }                    // Y
            const float* s0 = rsrc + (size_t)r0 * 3;
            const float* s1 = rsrc + (size_t)r1 * 3;
            q0x = s0[0]; q0y = s0[1]; q0z = s0[2];
            q1x = s1[0]; q1y = s1[1]; q1z = s1[2];
            if (addm) {
                const float* m0 = mh + ((size_t)b*NPTS + r0) * 3;
                const float* m1 = mh + ((size_t)b*NPTS + r1) * 3;
                q0x += m0[0]; q0y += m0[1]; q0z += m0[2];
                q1x += m1[0]; q1y += m1[1]; q1z += m1[2];
            }
        }
        const float w0 = q0x*q0x + q0y*q0y + q0z*q0z;
        const float w1 = q1x*q1x + q1y*q1y + q1z*q1z;
        const u64 p0x2 = pack2(q0x, q0x), p0y2 = pack2(q0y, q0y), p0z2 = pack2(q0z, q0z);
        const u64 p1x2 = pack2(q1x, q1x), p1y2 = pack2(q1y, q1y), p1z2 = pack2(q1z, q1z);

        __syncthreads();

        const int base = b * NPTS;

        if (task == 2) {
            float bA0 = 1e30f, bB0 = 1e30f, bA1 = 1e30f, bB1 = 1e30f;
            int   iA0 = 0, iB0 = 0, iA1 = 0, iB1 = 0;
#pragma unroll 4
            for (int j = 0; j < NPAIR_TILE; j++) {
                ulonglong2 xy = sA[j];
                ulonglong2 zw = sB[j];
                u64 a0 = fma2(xy.x, p0x2, fma2(xy.y, p0y2, fma2(zw.x, p0z2, zw.y)));
                u64 a1 = fma2(xy.x, p1x2, fma2(xy.y, p1y2, fma2(zw.x, p1z2, zw.y)));
                float l0, h0, l1, h1;
                unpack2(a0, l0, h0); unpack2(a1, l1, h1);
                bool c0 = l0 < bA0; iA0 = c0 ? j : iA0; bA0 = c0 ? l0 : bA0;
                bool c1 = h0 < bB0; iB0 = c1 ? j : iB0; bB0 = c1 ? h0 : bB0;
                bool c2 = l1 < bA1; iA1 = c2 ? j : iA1; bA1 = c2 ? l1 : bA1;
                bool c3 = h1 < bB1; iB1 = c3 ? j : iB1; bB1 = c3 ? h1 : bB1;
            }
            const int cbase = cc * COLS_PER_TILE;
            const int hslot = cc * BBN + base;
            {
                float bst = bA0; int idx = 2*iA0;
                float bo  = bB0; int io  = 2*iB0 + 1;
                if (bo < bst || (bo == bst && io < idx)) { bst = bo; idx = io; }
                HD(2, cc, base + r0) = fmaxf(bst + w0, 0.f);
                g_hidx[hslot + r0]   = cbase + idx;
            }
            {
                float bst = bA1; int idx = 2*iA1;
                float bo  = bB1; int io  = 2*iB1 + 1;
                if (bo < bst || (bo == bst && io < idx)) { bst = bo; idx = io; }
                HD(2, cc, base + r1) = fmaxf(bst + w1, 0.f);
                g_hidx[hslot + r1]   = cbase + idx;
            }
        } else {
            float bA0 = 1e30f, bB0 = 1e30f, bA1 = 1e30f, bB1 = 1e30f;
#pragma unroll 8
            for (int j = 0; j < NPAIR_TILE; j++) {
                ulonglong2 xy = sA[j];
                ulonglong2 zw = sB[j];
                u64 a0 = fma2(xy.x, p0x2, fma2(xy.y, p0y2, fma2(zw.x, p0z2, zw.y)));
                u64 a1 = fma2(xy.x, p1x2, fma2(xy.y, p1y2, fma2(zw.x, p1z2, zw.y)));
                float l0, h0, l1, h1;
                unpack2(a0, l0, h0); unpack2(a1, l1, h1);
                bA0 = fminf(bA0, l0); bB0 = fminf(bB0, h0);
                bA1 = fminf(bA1, l1); bB1 = fminf(bB1, h1);
            }
            HD(task, cc, base + r0) = fmaxf(fminf(bA0, bB0) + w0, 0.f);
            HD(task, cc, base + r1) = fmaxf(fminf(bA1, bB1) + w1, 0.f);
        }
    }
}

// ---------------- K2: epilogue (1 row/thread) + last-block writeout --------
__global__ void __launch_bounds__(TPB2) k_epi(const float* __restrict__ y0h,
                                              const float* __restrict__ y1h,
                                              const float* __restrict__ mh,
                                              float* __restrict__ out) {
    const int t = threadIdx.x;
    const int i = blockIdx.x * TPB2 + t;     // row 0..8191
    const int ib = i >> 11;

    // combine 16 chunk partials per task
    float d1 = HD(0, 0, i), d2 = HD(1, 0, i), m3 = HD(3, 0, i), c1 = HD(4, 0, i);
#pragma unroll
    for (int q = 1; q < CC; q++) {
        d1 = fminf(d1, HD(0, q, i));
        d2 = fminf(d2, HD(1, q, i));
        m3 = fminf(m3, HD(3, q, i));
        c1 = fminf(c1, HD(4, q, i));
    }
    float m1 = HD(2, 0, i); int id = g_hidx[i];
#pragma unroll
    for (int q = 1; q < CC; q++) {          // ascending q: strict < keeps lowest idx
        float mq = HD(2, q, i);
        int   iq = g_hidx[q * BBN + i];
        if (mq < m1) { m1 = mq; id = iq; }
    }
    float m2 = fminf(m1, m3);

    float md = (sqrtf(m1) < 0.05f) ? 1.f : 0.f;
    float mn = (sqrtf(m2) > 0.2f)  ? 1.f : 0.f;
    float sv = (c1 < 0.1f) ? c1 : 0.f;
    float cv = (c1 < 0.1f) ? 1.f : 0.f;
    float ch = d1 + d2;

    float pdyn = 0.f, psta = 0.f;
#pragma unroll
    for (int k = 0; k < 3; k++) {
        float dy = y1h[(size_t)i*3 + k] - y0h[(size_t)i*3 + k];
        float nm = mh[((size_t)ib*NPTS + id)*3 + k];
        float e  = dy - nm;
        pdyn = fmaf(e, e, pdyn);
        float ss = dy * mn;
        psta = fmaf(ss, ss, psta);
    }
    pdyn *= md;                              // mc applied per-batch at writeout

#pragma unroll
    for (int o = 16; o; o >>= 1) {
        ch   += __shfl_xor_sync(0xffffffffu, ch,   o);
        sv   += __shfl_xor_sync(0xffffffffu, sv,   o);
        cv   += __shfl_xor_sync(0xffffffffu, cv,   o);
        pdyn += __shfl_xor_sync(0xffffffffu, pdyn, o);
        psta += __shfl_xor_sync(0xffffffffu, psta, o);
    }
    if ((t & 31) == 0) {                     // batch uniform per warp (128-row block)
        atomicAdd(&g_chamfer[ib], ch);
        atomicAdd(&g_dynb[ib], pdyn);
        atomicAdd(&g_stat, psta);
        atomicAdd(&g_sumd, sv);
        atomicAdd(&g_cntd, (int)cv);
    }

    __syncthreads();
    if (t == 0) {
        __threadfence();
        int old = atomicAdd(&g_done, 1);
        if (old == NBLK2 - 1) {              // last block: writeout + reset
            __threadfence();
            const float inv = 1.f / (float)(BB * NPTS * 3);
            float dyn = 0.f;
#pragma unroll
            for (int bb = 0; bb < BB; bb++) {
                float mc = ((g_chamfer[bb] * (1.f / NPTS)) < 0.1f) ? 1.f : 0.f;
                dyn += mc * g_dynb[bb];
            }
            out[0] = dyn * inv;
            out[1] = g_stat * inv;
            out[2] = g_sumd / fmaxf((float)g_cntd, 1.f);
#pragma unroll
            for (int bb = 0; bb < BB; bb++) { g_chamfer[bb] = 0.f; g_dynb[bb] = 0.f; }
            g_stat = 0.f; g_sumd = 0.f; g_cntd = 0;
            g_done = 0;
            __threadfence();
        }
    }
}

// ---------------- launch: 2 kernels ----------------
extern "C" void kernel_launch(void* const* d_in, const int* in_sizes, int n_in,
                              void* d_out, int out_size) {
    const float* x   = (const float*)d_in[0];  // (B,2,N,3)
    const float* mh  = (const float*)d_in[1];  // (B,1,N,3)
    const float* y0h = (const float*)d_in[2];  // (B,1,M,3)
    const float* y1h = (const float*)d_in[3];  // (B,1,M,3)
    float* out = (float*)d_out;

    k_pair<<<NBLK1, TPB>>>(x, mh, y0h);
    k_epi <<<NBLK2, TPB2>>>(y0h, y1h, mh, out);
}

// round 11
// speedup vs baseline: 2.2318x; 1.1605x over previous
#include <cuda_runtime.h>

#define BB    4
#define NPTS  2048
#define BBN   (BB * NPTS)
#define TPB   256
#define RC    4                      // row chunks (512 rows each)
#define CC    16                     // column chunks (128 cols each)
#define NTILE (5 * BB * RC * CC)     // 1280 tiles
#define NBLK1 444                    // K1 blocks (3 per SM)
#define ROWS_PER_TILE (NPTS / RC)    // 512 = 2 * TPB
#define COLS_PER_TILE (NPTS / CC)    // 128
#define NPAIR_TILE (COLS_PER_TILE/2) // 64 pairs staged
#define NBLK2 64                     // K2 blocks
#define TPB2  128

typedef unsigned long long u64;
typedef unsigned int       u32;

// ---- reduction arrays, identity = 0 (inverted-bits max == min over d>=0) --
// zeroed at module load; k_epi resets its own rows after reading each replay.
__device__ u32 g_rm[5 * BBN];        // [task][row]  ~bits(d)   (task 2 unused)
__device__ u64 g_am[BBN];            // task2: ~((dbits<<32)|idx)
// scalar accumulators: zero at load, reset by last k_epi block
__device__ float g_chamfer[BB];
__device__ float g_dynb[BB];
__device__ float g_stat;
__device__ float g_sumd;
__device__ int   g_cntd;
__device__ int   g_done;

// ---------------- f32x2 helpers ----------------
__device__ __forceinline__ u64 pack2(float lo, float hi) {
    u64 r; asm("mov.b64 %0, {%1,%2};" : "=l"(r) : "f"(lo), "f"(hi)); return r;
}
__device__ __forceinline__ void unpack2(u64 v, float& lo, float& hi) {
    asm("mov.b64 {%0,%1}, %2;" : "=f"(lo), "=f"(hi) : "l"(v));
}
__device__ __forceinline__ u64 fma2(u64 a, u64 b, u64 c) {
    u64 d; asm("fma.rn.f32x2 %0, %1, %2, %3;" : "=l"(d) : "l"(a), "l"(b), "l"(c)); return d;
}

// ---------------- K1: pairwise over fine tiles, RED.MAX combine -----------
// task 0: rows PH, cols P1   task 1: rows P1, cols PH
// task 2: rows Y,  cols P0 (argmin)   task 3: rows Y, cols P1
// task 4: rows P0, cols Y
__global__ void __launch_bounds__(TPB, 3) k_pair(const float* __restrict__ x,
                                                 const float* __restrict__ mh,
                                                 const float* __restrict__ y0) {
    __shared__ ulonglong2 sA[NPAIR_TILE];   // (x0,x1),(y0,y1) scaled by -2
    __shared__ ulonglong2 sB[NPAIR_TILE];   // (z0,z1),(w0,w1) w=|q|^2
    const int t = threadIdx.x;

    for (int tau = blockIdx.x; tau < NTILE; tau += NBLK1) {
        const int task = tau >> 8;
        const int rem  = tau & 255;
        const int b    = rem >> 6;
        const int rc   = (rem >> 4) & 3;
        const int cc   = rem & 15;

        // ---- stage 128 columns (64 pairs), pre-scaled ----
        __syncthreads();                    // protect smem from previous tile
        if (t < NPAIR_TILE) {
            const float* src; bool addm = false;
            if (task == 1)      { src = x  + (size_t)(b*2+0)*NPTS*3; addm = true; }  // PH
            else if (task == 2) { src = x  + (size_t)(b*2+0)*NPTS*3; }               // P0
            else if (task == 4) { src = y0 + (size_t)b*NPTS*3; }                     // Y
            else                { src = x  + (size_t)(b*2+1)*NPTS*3; }               // P1
            int gp = cc * NPAIR_TILE + t;
            const float2* s2 = (const float2*)(src + (size_t)2 * gp * 3);
            float2 aa = s2[0], bb = s2[1], cc2 = s2[2];
            float px0 = aa.x, py0 = aa.y, pz0 = bb.x;
            float px1 = bb.y, py1 = cc2.x, pz1 = cc2.y;
            if (addm) {
                const float2* m2p = (const float2*)(mh + ((size_t)b*NPTS + 2*gp) * 3);
                float2 ma = m2p[0], mb2 = m2p[1], mc = m2p[2];
                px0 += ma.x;  py0 += ma.y;  pz0 += mb2.x;
                px1 += mb2.y; py1 += mc.x;  pz1 += mc.y;
            }
            float w0c = px0*px0 + py0*py0 + pz0*pz0;
            float w1c = px1*px1 + py1*py1 + pz1*pz1;
            sA[t] = make_ulonglong2(pack2(-2.f*px0, -2.f*px1), pack2(-2.f*py0, -2.f*py1));
            sB[t] = make_ulonglong2(pack2(-2.f*pz0, -2.f*pz1), pack2(w0c, w1c));
        }

        // ---- this thread's 2 rows ----
        const int r0 = rc * ROWS_PER_TILE + t;
        const int r1 = r0 + TPB;
        float q0x, q0y, q0z, q1x, q1y, q1z;
        {
            const float* rsrc; bool addm = false;
            if (task == 0)      { rsrc = x  + (size_t)(b*2+0)*NPTS*3; addm = true; } // PH
            else if (task == 1) { rsrc = x  + (size_t)(b*2+1)*NPTS*3; }              // P1
            else if (task == 4) { rsrc = x  + (size_t)(b*2+0)*NPTS*3; }              // P0
            else                { rsrc = y0 + (size_t)b*NPTS*3; }                    // Y
            const float* s0 = rsrc + (size_t)r0 * 3;
            const float* s1 = rsrc + (size_t)r1 * 3;
            q0x = s0[0]; q0y = s0[1]; q0z = s0[2];
            q1x = s1[0]; q1y = s1[1]; q1z = s1[2];
            if (addm) {
                const float* m0 = mh + ((size_t)b*NPTS + r0) * 3;
                const float* m1 = mh + ((size_t)b*NPTS + r1) * 3;
                q0x += m0[0]; q0y += m0[1]; q0z += m0[2];
                q1x += m1[0]; q1y += m1[1]; q1z += m1[2];
            }
        }
        const float w0 = q0x*q0x + q0y*q0y + q0z*q0z;
        const float w1 = q1x*q1x + q1y*q1y + q1z*q1z;
        const u64 p0x2 = pack2(q0x, q0x), p0y2 = pack2(q0y, q0y), p0z2 = pack2(q0z, q0z);
        const u64 p1x2 = pack2(q1x, q1x), p1y2 = pack2(q1y, q1y), p1z2 = pack2(q1z, q1z);

        __syncthreads();

        const int base = b * NPTS;

        if (task == 2) {
            float bA0 = 1e30f, bB0 = 1e30f, bA1 = 1e30f, bB1 = 1e30f;
            int   iA0 = 0, iB0 = 0, iA1 = 0, iB1 = 0;
#pragma unroll 4
            for (int j = 0; j < NPAIR_TILE; j++) {
                ulonglong2 xy = sA[j];
                ulonglong2 zw = sB[j];
                u64 a0 = fma2(xy.x, p0x2, fma2(xy.y, p0y2, fma2(zw.x, p0z2, zw.y)));
                u64 a1 = fma2(xy.x, p1x2, fma2(xy.y, p1y2, fma2(zw.x, p1z2, zw.y)));
                float l0, h0, l1, h1;
                unpack2(a0, l0, h0); unpack2(a1, l1, h1);
                bool c0 = l0 < bA0; iA0 = c0 ? j : iA0; bA0 = c0 ? l0 : bA0;
                bool c1 = h0 < bB0; iB0 = c1 ? j : iB0; bB0 = c1 ? h0 : bB0;
                bool c2 = l1 < bA1; iA1 = c2 ? j : iA1; bA1 = c2 ? l1 : bA1;
                bool c3 = h1 < bB1; iB1 = c3 ? j : iB1; bB1 = c3 ? h1 : bB1;
            }
            const int cbase = cc * COLS_PER_TILE;
            {
                float bst = bA0; int idx = 2*iA0;
                float bo  = bB0; int io  = 2*iB0 + 1;
                if (bo < bst || (bo == bst && io < idx)) { bst = bo; idx = io; }
                float d = fmaxf(bst + w0, 0.f);
                u64 pk = ((u64)__float_as_uint(d) << 32) | (u32)(cbase + idx);
                atomicMax(&g_am[base + r0], ~pk);
            }
            {
                float bst = bA1; int idx = 2*iA1;
                float bo  = bB1; int io  = 2*iB1 + 1;
                if (bo < bst || (bo == bst && io < idx)) { bst = bo; idx = io; }
                float d = fmaxf(bst + w1, 0.f);
                u64 pk = ((u64)__float_as_uint(d) << 32) | (u32)(cbase + idx);
                atomicMax(&g_am[base + r1], ~pk);
            }
        } else {
            float bA0 = 1e30f, bB0 = 1e30f, bA1 = 1e30f, bB1 = 1e30f;
#pragma unroll 8
            for (int j = 0; j < NPAIR_TILE; j++) {
                ulonglong2 xy = sA[j];
                ulonglong2 zw = sB[j];
                u64 a0 = fma2(xy.x, p0x2, fma2(xy.y, p0y2, fma2(zw.x, p0z2, zw.y)));
                u64 a1 = fma2(xy.x, p1x2, fma2(xy.y, p1y2, fma2(zw.x, p1z2, zw.y)));
                float l0, h0, l1, h1;
                unpack2(a0, l0, h0); unpack2(a1, l1, h1);
                bA0 = fminf(bA0, l0); bB0 = fminf(bB0, h0);
                bA1 = fminf(bA1, l1); bB1 = fminf(bB1, h1);
            }
            float d0 = fmaxf(fminf(bA0, bB0) + w0, 0.f);
            float d1 = fmaxf(fminf(bA1, bB1) + w1, 0.f);
            u32* arr = g_rm + task * BBN + base;
            atomicMax(&arr[r0], ~__float_as_uint(d0));
            atomicMax(&arr[r1], ~__float_as_uint(d1));
        }
    }
}

// ---------------- K2: epilogue (1 row/thread, 5 scratch loads) ------------
__global__ void __launch_bounds__(TPB2) k_epi(const float* __restrict__ y0h,
                                              const float* __restrict__ y1h,
                                              const float* __restrict__ mh,
                                              float* __restrict__ out) {
    const int t = threadIdx.x;
    const int i = blockIdx.x * TPB2 + t;     // row 0..8191
    const int ib = i >> 11;

    float d1 = __uint_as_float(~g_rm[0*BBN + i]);
    float d2 = __uint_as_float(~g_rm[1*BBN + i]);
    float m3 = __uint_as_float(~g_rm[3*BBN + i]);
    float c1 = __uint_as_float(~g_rm[4*BBN + i]);
    u64 pk = ~g_am[i];
    float m1 = __uint_as_float((u32)(pk >> 32));
    int   id = (int)(u32)pk;
    float m2 = fminf(m1, m3);

    // reset scratch for next replay (this kernel is the last reader)
    g_rm[0*BBN + i] = 0u; g_rm[1*BBN + i] = 0u;
    g_rm[3*BBN + i] = 0u; g_rm[4*BBN + i] = 0u;
    g_am[i] = 0ull;

    float md = (sqrtf(m1) < 0.05f) ? 1.f : 0.f;
    float mn = (sqrtf(m2) > 0.2f)  ? 1.f : 0.f;
    float sv = (c1 < 0.1f) ? c1 : 0.f;
    float cv = (c1 < 0.1f) ? 1.f : 0.f;
    float ch = d1 + d2;

    float pdyn = 0.f, psta = 0.f;
#pragma unroll
    for (int k = 0; k < 3; k++) {
        float dy = y1h[(size_t)i*3 + k] - y0h[(size_t)i*3 + k];
        float nm = mh[((size_t)ib*NPTS + id)*3 + k];
        float e  = dy - nm;
        pdyn = fmaf(e, e, pdyn);
        float ss = dy * mn;
        psta = fmaf(ss, ss, psta);
    }
    pdyn *= md;                              // mc applied per-batch at writeout

#pragma unroll
    for (int o = 16; o; o >>= 1) {
        ch   += __shfl_xor_sync(0xffffffffu, ch,   o);
        sv   += __shfl_xor_sync(0xffffffffu, sv,   o);
        cv   += __shfl_xor_sync(0xffffffffu, cv,   o);
        pdyn += __shfl_xor_sync(0xffffffffu, pdyn, o);
        psta += __shfl_xor_sync(0xffffffffu, psta, o);
    }
    if ((t & 31) == 0) {                     // batch uniform per warp (128-row block)
        atomicAdd(&g_chamfer[ib], ch);
        atomicAdd(&g_dynb[ib], pdyn);
        atomicAdd(&g_stat, psta);
        atomicAdd(&g_sumd, sv);
        atomicAdd(&g_cntd, (int)cv);
    }

    __syncthreads();
    if (t == 0) {
        __threadfence();
        int old = atomicAdd(&g_done, 1);
        if (old == NBLK2 - 1) {              // last block: writeout + reset
            __threadfence();
            const float inv = 1.f / (float)(BB * NPTS * 3);
            float dyn = 0.f;
#pragma unroll
            for (int bb = 0; bb < BB; bb++) {
                float mc = ((g_chamfer[bb] * (1.f / NPTS)) < 0.1f) ? 1.f : 0.f;
                dyn += mc * g_dynb[bb];
            }
            out[0] = dyn * inv;
            out[1] = g_stat * inv;
            out[2] = g_sumd / fmaxf((float)g_cntd, 1.f);
#pragma unroll
            for (int bb = 0; bb < BB; bb++) { g_chamfer[bb] = 0.f; g_dynb[bb] = 0.f; }
            g_stat = 0.f; g_sumd = 0.f; g_cntd = 0;
            g_done = 0;
            __threadfence();
        }
    }
}

// ---------------- launch: 2 kernels ----------------
extern "C" void kernel_launch(void* const* d_in, const int* in_sizes, int n_in,
                              void* d_out, int out_size) {
    const float* x   = (const float*)d_in[0];  // (B,2,N,3)
    const float* mh  = (const float*)d_in[1];  // (B,1,N,3)
    const float* y0h = (const float*)d_in[2];  // (B,1,M,3)
    const float* y1h = (const float*)d_in[3];  // (B,1,M,3)
    float* out = (float*)d_out;

    k_pair<<<NBLK1, TPB>>>(x, mh, y0h);
    k_epi <<<NBLK2, TPB2>>>(y0h, y1h, mh, out);
}